// round 2
// baseline (speedup 1.0000x reference)
#include <cuda_runtime.h>
#include <math.h>

// Problem constants
#define BATCH   128
#define TSTEPS  256
#define BT      32768          // BATCH*TSTEPS
#define HCAT    1024           // 512+256+256

// ---------------- scratch (device globals; no allocation allowed) -------------
__device__ float g_gx0[(size_t)BT * 2048];   // layer0 input proj (i,f,g,o)
__device__ float g_gx1[(size_t)BT * 1024];   // layer1
__device__ float g_gx2[(size_t)BT * 1024];   // layer2
__device__ float g_hcat[(size_t)BT * HCAT];  // hidden trajectories, [b][t][1024]
__device__ float g_z[(size_t)BT * 256];      // FC1 output
__device__ unsigned int g_bar;               // grid barrier counter

__global__ void reset_kernel() { g_bar = 0u; }

// ------------------------------------------------------------------------------
// Generic C[M,N] = A[M,K] @ W[N,K]^T + b1 (+ b2) (+relu)
// a_sel: 0 -> A = g_hcat, else use Aext.  c_sel: 0..2 -> g_gx*, 3 -> g_z
// BM=64, BN=64, BK=16, 256 threads, 4x4 per thread.
// ------------------------------------------------------------------------------
__global__ __launch_bounds__(256) void gemm_xwt(
    const float* __restrict__ Aext, int a_sel,
    const float* __restrict__ W,
    const float* __restrict__ b1, const float* __restrict__ b2,
    int c_sel, int M, int N, int K, int relu)
{
    __shared__ float As[16][64];
    __shared__ float Bs[16][64];

    const float* A = (a_sel == 0) ? g_hcat : Aext;
    float* C;
    if      (c_sel == 0) C = g_gx0;
    else if (c_sel == 1) C = g_gx1;
    else if (c_sel == 2) C = g_gx2;
    else                 C = g_z;

    const int tid = threadIdx.x;
    const int jg  = tid & 15;        // output col group
    const int bg  = tid >> 4;        // output row group
    const int m0g = blockIdx.y * 64;
    const int n0g = blockIdx.x * 64;
    const int lm  = tid >> 2;        // 0..63 (load row)
    const int lk  = (tid & 3) << 2;  // 0,4,8,12

    float acc[4][4];
    #pragma unroll
    for (int i = 0; i < 4; i++)
        #pragma unroll
        for (int j = 0; j < 4; j++) acc[i][j] = 0.f;

    const int ktiles = (K + 15) >> 4;
    for (int kt = 0; kt < ktiles; kt++) {
        const int kb = kt << 4;
        #pragma unroll
        for (int i = 0; i < 4; i++) {
            const int k = kb + lk + i;
            As[lk + i][lm] = (k < K) ? A[(size_t)(m0g + lm) * K + k] : 0.f;
            Bs[lk + i][lm] = (k < K) ? W[(size_t)(n0g + lm) * K + k] : 0.f;
        }
        __syncthreads();
        #pragma unroll
        for (int k = 0; k < 16; k++) {
            const float4 a = *(const float4*)&As[k][bg << 2];
            const float4 b = *(const float4*)&Bs[k][jg << 2];
            const float av[4] = {a.x, a.y, a.z, a.w};
            const float bv[4] = {b.x, b.y, b.z, b.w};
            #pragma unroll
            for (int i = 0; i < 4; i++)
                #pragma unroll
                for (int j = 0; j < 4; j++)
                    acc[i][j] = fmaf(av[i], bv[j], acc[i][j]);
        }
        __syncthreads();
    }

    #pragma unroll
    for (int j = 0; j < 4; j++) {
        const int n = n0g + (jg << 2) + j;
        float bias = b1[n];
        if (b2) bias += b2[n];
        #pragma unroll
        for (int i = 0; i < 4; i++) {
            const int m = m0g + (bg << 2) + i;
            float v = acc[i][j] + bias;
            if (relu) v = fmaxf(v, 0.f);
            C[(size_t)m * N + n] = v;
        }
    }
}

// ------------------------------------------------------------------------------
// Persistent LSTM recurrence. 128 CTAs x 256 threads; one merged grid barrier
// per timestep. Each CTA owns: unit A = 4 cells of layer0 (K=512) and
// unit B = 4 cells of layer1 (cta<64) or layer2 (cta>=64) (K=256).
// Gate columns per unit: jj = g*4 + cc for gate g in {i,f,g,o}, cell cc in 0..3.
// ------------------------------------------------------------------------------
__device__ __forceinline__ float sigf(float x) { return 1.f / (1.f + expf(-x)); }

__global__ __launch_bounds__(256, 1) void lstm_rec(
    const float* __restrict__ Whh0,
    const float* __restrict__ Whh1,
    const float* __restrict__ Whh2)
{
    __shared__ float h_s[32][128];   // [k][b]
    __shared__ float w_s[32][16];    // [k][jj]
    __shared__ float g_s[16][128];   // [jj][b] gate preactivations
    __shared__ float c_s[2][4][128]; // [unit][cell][b]

    const int cta = blockIdx.x;
    const int tid = threadIdx.x;

    // unit A: layer 0
    const int   cbA = cta * 4;
    // unit B: layer 1 or 2
    const float* WB;  int coloffB, cbB;  const float* gxB;
    if (cta < 64) { WB = Whh1; coloffB = 512; cbB = cta * 4;        gxB = g_gx1; }
    else          { WB = Whh2; coloffB = 768; cbB = (cta - 64) * 4; gxB = g_gx2; }

    for (int i = tid; i < 2 * 4 * 128; i += 256) ((float*)c_s)[i] = 0.f;
    __syncthreads();

    const int jg   = tid & 7;          // compute: j0 = jg*2
    const int bg   = tid >> 3;         // compute: b0 = bg*4
    const int b_ld = tid >> 1;         // h load: batch row
    const int kh   = (tid & 1) * 16;   // h load: k offset
    const int jj_w = tid & 15;         // w load: gate column
    const int kq   = tid >> 4;         // w load: k pair index (0..15)
    const int b_e  = tid & 127;        // epilogue batch
    const int hsel = tid >> 7;         // epilogue half (0/1)

    for (int t = 0; t < TSTEPS; t++) {
        #pragma unroll 1
        for (int u = 0; u < 2; u++) {
            const float* Whh   = u ? WB      : Whh0;
            const float* gx    = u ? gxB     : g_gx0;
            const int    K     = u ? 256     : 512;
            const int    coloff= u ? coloffB : 0;
            const int    cb    = u ? cbB     : cbA;
            const int    fourh = u ? 1024    : 2048;
            const int    h     = u ? 256     : 512;

            // stage gx[b, t, 16 cols] into g_s
            #pragma unroll
            for (int cpass = 0; cpass < 2; cpass++) {
                const int g = hsel + cpass * 2;
                const float4 v = *(const float4*)&gx[(size_t)(b_e * TSTEPS + t) * fourh + g * h + cb];
                g_s[g * 4 + 0][b_e] = v.x;
                g_s[g * 4 + 1][b_e] = v.y;
                g_s[g * 4 + 2][b_e] = v.z;
                g_s[g * 4 + 3][b_e] = v.w;
            }

            if (t > 0) {
                float acc[4][2];
                #pragma unroll
                for (int i = 0; i < 4; i++) { acc[i][0] = 0.f; acc[i][1] = 0.f; }

                const int gch = jj_w >> 2, ccw = jj_w & 3;
                const float* wrow = &Whh[(size_t)(gch * h + cb + ccw) * K];

                for (int kt = 0; kt < K; kt += 32) {
                    // h tile: [32 k][128 b], coalesced global reads
                    const float* hrow = &g_hcat[(size_t)(b_ld * TSTEPS + (t - 1)) * HCAT + coloff + kt + kh];
                    #pragma unroll
                    for (int q = 0; q < 4; q++) {
                        const float4 v = *(const float4*)&hrow[q * 4];
                        h_s[kh + q * 4 + 0][b_ld] = v.x;
                        h_s[kh + q * 4 + 1][b_ld] = v.y;
                        h_s[kh + q * 4 + 2][b_ld] = v.z;
                        h_s[kh + q * 4 + 3][b_ld] = v.w;
                    }
                    // w tile
                    {
                        const float2 wv = *(const float2*)&wrow[kt + kq * 2];
                        w_s[kq * 2 + 0][jj_w] = wv.x;
                        w_s[kq * 2 + 1][jj_w] = wv.y;
                    }
                    __syncthreads();
                    #pragma unroll
                    for (int k = 0; k < 32; k++) {
                        const float4 a = *(const float4*)&h_s[k][bg << 2];
                        const float2 w = *(const float2*)&w_s[k][jg << 1];
                        acc[0][0] = fmaf(a.x, w.x, acc[0][0]);
                        acc[1][0] = fmaf(a.y, w.x, acc[1][0]);
                        acc[2][0] = fmaf(a.z, w.x, acc[2][0]);
                        acc[3][0] = fmaf(a.w, w.x, acc[3][0]);
                        acc[0][1] = fmaf(a.x, w.y, acc[0][1]);
                        acc[1][1] = fmaf(a.y, w.y, acc[1][1]);
                        acc[2][1] = fmaf(a.z, w.y, acc[2][1]);
                        acc[3][1] = fmaf(a.w, w.y, acc[3][1]);
                    }
                    __syncthreads();
                }
                // accumulate into g_s (exclusive ownership per (jj,b))
                #pragma unroll
                for (int ji = 0; ji < 2; ji++)
                    #pragma unroll
                    for (int bi = 0; bi < 4; bi++)
                        g_s[(jg << 1) + ji][(bg << 2) + bi] += acc[bi][ji];
            }
            __syncthreads();

            // cell update: thread handles (b_e, cells hsel*2 and hsel*2+1)
            #pragma unroll
            for (int cp = 0; cp < 2; cp++) {
                const int cc = hsel * 2 + cp;
                const float gi = g_s[ 0 + cc][b_e];
                const float gf = g_s[ 4 + cc][b_e];
                const float gg = g_s[ 8 + cc][b_e];
                const float go = g_s[12 + cc][b_e];
                const float cold = c_s[u][cc][b_e];
                const float cn = sigf(gf) * cold + sigf(gi) * tanhf(gg);
                const float hn = sigf(go) * tanhf(cn);
                c_s[u][cc][b_e] = cn;
                g_hcat[(size_t)(b_e * TSTEPS + t) * HCAT + coloff + cb + cc] = hn;
            }
            __syncthreads();
        }

        // ---- merged grid barrier across the 128 resident CTAs ----
        __threadfence();
        __syncthreads();
        if (tid == 0) {
            atomicAdd(&g_bar, 1u);
            const unsigned target = 128u * (unsigned)(t + 1);
            while (*(volatile unsigned*)&g_bar < target) { }
            __threadfence();
        }
        __syncthreads();
    }
}

// ------------------------------------------------------------------------------
// FC2 (7x256) + log_softmax, one warp per (b,t) row.
// ------------------------------------------------------------------------------
__global__ __launch_bounds__(256) void fc2_softmax(
    const float* __restrict__ W2, const float* __restrict__ b2,
    float* __restrict__ out)
{
    const int warp = threadIdx.x >> 5, lane = threadIdx.x & 31;
    const int row = blockIdx.x * 8 + warp;   // 0..32767
    const float4* z4 = (const float4*)&g_z[(size_t)row * 256];
    const float4 z0 = z4[lane];
    const float4 z1 = z4[32 + lane];

    float logit[7];
    #pragma unroll
    for (int o = 0; o < 7; o++) {
        const float4* w4 = (const float4*)&W2[o * 256];
        const float4 w0 = w4[lane], w1 = w4[32 + lane];
        float p = z0.x * w0.x + z0.y * w0.y + z0.z * w0.z + z0.w * w0.w
                + z1.x * w1.x + z1.y * w1.y + z1.z * w1.z + z1.w * w1.w;
        #pragma unroll
        for (int s = 16; s > 0; s >>= 1) p += __shfl_xor_sync(0xffffffffu, p, s);
        logit[o] = p + b2[o];
    }
    float m = logit[0];
    #pragma unroll
    for (int o = 1; o < 7; o++) m = fmaxf(m, logit[o]);
    float se = 0.f;
    #pragma unroll
    for (int o = 0; o < 7; o++) se += expf(logit[o] - m);
    const float lse = logf(se);
    if (lane < 7) out[(size_t)row * 7 + lane] = logit[lane] - m - lse;
}

// ------------------------------------------------------------------------------
extern "C" void kernel_launch(void* const* d_in, const int* in_sizes, int n_in,
                              void* d_out, int out_size)
{
    const float* x0    = (const float*)d_in[0];
    const float* x1    = (const float*)d_in[1];
    const float* x2    = (const float*)d_in[2];
    const float* Wih0  = (const float*)d_in[3];
    const float* Whh0  = (const float*)d_in[4];
    const float* bih0  = (const float*)d_in[5];
    const float* bhh0  = (const float*)d_in[6];
    const float* Wih1  = (const float*)d_in[7];
    const float* Whh1  = (const float*)d_in[8];
    const float* bih1  = (const float*)d_in[9];
    const float* bhh1  = (const float*)d_in[10];
    const float* Wih2  = (const float*)d_in[11];
    const float* Whh2  = (const float*)d_in[12];
    const float* bih2  = (const float*)d_in[13];
    const float* bhh2  = (const float*)d_in[14];
    const float* fcW1  = (const float*)d_in[15];
    const float* fcb1  = (const float*)d_in[16];
    const float* fcW2  = (const float*)d_in[17];
    const float* fcb2  = (const float*)d_in[18];
    float* out = (float*)d_out;

    reset_kernel<<<1, 1>>>();

    // input projections: gx = x @ W_ih^T + b_ih + b_hh
    { dim3 g(2048 / 64, BT / 64); gemm_xwt<<<g, 256>>>(x0, -1, Wih0, bih0, bhh0, 0, BT, 2048, 300, 0); }
    { dim3 g(1024 / 64, BT / 64); gemm_xwt<<<g, 256>>>(x1, -1, Wih1, bih1, bhh1, 1, BT, 1024,  74, 0); }
    { dim3 g(1024 / 64, BT / 64); gemm_xwt<<<g, 256>>>(x2, -1, Wih2, bih2, bhh2, 2, BT, 1024,  35, 0); }

    // persistent recurrence over T=256 (all three LSTMs, merged barrier)
    lstm_rec<<<128, 256>>>(Whh0, Whh1, Whh2);

    // FC1 + ReLU: z = relu(hcat @ fc_W1^T + fc_b1)
    { dim3 g(256 / 64, BT / 64); gemm_xwt<<<g, 256>>>(nullptr, 0, fcW1, fcb1, nullptr, 3, BT, 256, 1024, 1); }

    // FC2 + log_softmax
    fc2_softmax<<<BT / 8, 256>>>(fcW2, fcb2, out);
}

// round 6
// speedup vs baseline: 2.0998x; 2.0998x over previous
#include <cuda_runtime.h>
#include <math.h>

// Problem constants
#define BATCH   128
#define TSTEPS  256
#define BT      32768          // BATCH*TSTEPS
#define HCAT    1024           // 512+256+256

// ---------------- scratch (device globals; no allocation allowed) -------------
__device__ float g_gx0[(size_t)BT * 2048];   // layer0 input proj (i,f,g,o)
__device__ float g_gx1[(size_t)BT * 1024];   // layer1
__device__ float g_gx2[(size_t)BT * 1024];   // layer2
__device__ float g_hcat[(size_t)BT * HCAT];  // hidden trajectories fp32, [b][t][1024]
__device__ float g_z[(size_t)BT * 256];      // FC1 output
__device__ float g_hb[2][131072];            // recurrent h, tf32, mma-fragment layout, double buffered
__device__ unsigned int g_bar;               // grid barrier counter

__global__ void reset_kernel() { g_bar = 0u; }

// ------------------------------------------------------------------------------
// Generic C[M,N] = A[M,K] @ W[N,K]^T + b1 (+ b2) (+relu)   (unchanged)
// ------------------------------------------------------------------------------
__global__ __launch_bounds__(256) void gemm_xwt(
    const float* __restrict__ Aext, int a_sel,
    const float* __restrict__ W,
    const float* __restrict__ b1, const float* __restrict__ b2,
    int c_sel, int M, int N, int K, int relu)
{
    __shared__ float As[16][64];
    __shared__ float Bs[16][64];

    const float* A = (a_sel == 0) ? g_hcat : Aext;
    float* C;
    if      (c_sel == 0) C = g_gx0;
    else if (c_sel == 1) C = g_gx1;
    else if (c_sel == 2) C = g_gx2;
    else                 C = g_z;

    const int tid = threadIdx.x;
    const int jg  = tid & 15;
    const int bg  = tid >> 4;
    const int m0g = blockIdx.y * 64;
    const int n0g = blockIdx.x * 64;
    const int lm  = tid >> 2;
    const int lk  = (tid & 3) << 2;

    float acc[4][4];
    #pragma unroll
    for (int i = 0; i < 4; i++)
        #pragma unroll
        for (int j = 0; j < 4; j++) acc[i][j] = 0.f;

    const int ktiles = (K + 15) >> 4;
    for (int kt = 0; kt < ktiles; kt++) {
        const int kb = kt << 4;
        #pragma unroll
        for (int i = 0; i < 4; i++) {
            const int k = kb + lk + i;
            As[lk + i][lm] = (k < K) ? A[(size_t)(m0g + lm) * K + k] : 0.f;
            Bs[lk + i][lm] = (k < K) ? W[(size_t)(n0g + lm) * K + k] : 0.f;
        }
        __syncthreads();
        #pragma unroll
        for (int k = 0; k < 16; k++) {
            const float4 a = *(const float4*)&As[k][bg << 2];
            const float4 b = *(const float4*)&Bs[k][jg << 2];
            const float av[4] = {a.x, a.y, a.z, a.w};
            const float bv[4] = {b.x, b.y, b.z, b.w};
            #pragma unroll
            for (int i = 0; i < 4; i++)
                #pragma unroll
                for (int j = 0; j < 4; j++)
                    acc[i][j] = fmaf(av[i], bv[j], acc[i][j]);
        }
        __syncthreads();
    }

    #pragma unroll
    for (int j = 0; j < 4; j++) {
        const int n = n0g + (jg << 2) + j;
        float bias = b1[n];
        if (b2) bias += b2[n];
        #pragma unroll
        for (int i = 0; i < 4; i++) {
            const int m = m0g + (bg << 2) + i;
            float v = acc[i][j] + bias;
            if (relu) v = fmaxf(v, 0.f);
            C[(size_t)m * N + n] = v;
        }
    }
}

// ------------------------------------------------------------------------------
// tf32 helpers
// ------------------------------------------------------------------------------
__device__ __forceinline__ float to_tf32(float x) {
    float r; asm("cvt.rna.tf32.f32 %0, %1;" : "=f"(r) : "f"(x)); return r;
}

__device__ __forceinline__ void mma8(float (&d)[4],
                                     float a0, float a1, float a2, float a3,
                                     float b0, float b1) {
    asm volatile("mma.sync.aligned.m16n8k8.row.col.f32.tf32.tf32.f32 "
                 "{%0,%1,%2,%3}, {%4,%5,%6,%7}, {%8,%9}, {%0,%1,%2,%3};"
                 : "+f"(d[0]), "+f"(d[1]), "+f"(d[2]), "+f"(d[3])
                 : "r"(__float_as_uint(a0)), "r"(__float_as_uint(a1)),
                   "r"(__float_as_uint(a2)), "r"(__float_as_uint(a3)),
                   "r"(__float_as_uint(b0)), "r"(__float_as_uint(b1)));
}

__device__ __forceinline__ float sigf(float x) { return 1.f / (1.f + expf(-x)); }

// ------------------------------------------------------------------------------
// Persistent LSTM recurrence (tensor-core tf32 mma version).
// 128 CTAs x 256 threads, 1 grid barrier/step.
// CTA owns 4 cells of layer0 (unit A, warps 0-3) and 4 cells of layer1/2
// (unit B, warps 4-7). Warp covers 32 batch rows x 16 gate cols.
// Weights live in smem (fragment-pair permuted, tf32-rounded) for all steps.
// h trajectory: fp32 -> g_hcat; tf32 fragment-layout -> g_hb[t&1].
//
// g_hb layout: per layer, tiles of (16 batch x 16 k): tile(layer, blk, kg),
// 256 floats each; within tile: off = half*128 + lane*4 + e, where
// half = rloc>>3, lane = (rloc&7)*4 + (k16&3), e = k16>>2.
// Reader: two coalesced 512B LDG.128.cg per (M-tile, k16-group).
// ------------------------------------------------------------------------------
__global__ void __launch_bounds__(256, 1) lstm_rec(
    const float* __restrict__ Whh0,
    const float* __restrict__ Whh1,
    const float* __restrict__ Whh2)
{
    extern __shared__ float sm[];
    float* wsA = sm;                     // [16][516]
    float* wsB = wsA + 16 * 516;         // [16][260]
    float* gsA = wsB + 16 * 260;         // [16][132]
    float* gsB = gsA + 16 * 132;         // [16][132]
    float* csm = gsB + 16 * 132;         // [2][4][128]

    const int cta = blockIdx.x, tid = threadIdx.x;
    const int lane = tid & 31, w = tid >> 5;
    const int cbA = cta * 4;

    const float* WB; const float* gxB; int coloffB, cbB, lbaseB;
    if (cta < 64) { WB = Whh1; gxB = g_gx1; coloffB = 512; cbB = cta * 4;        lbaseB = 65536; }
    else          { WB = Whh2; gxB = g_gx2; coloffB = 768; cbB = (cta - 64) * 4; lbaseB = 98304; }

    // ---- one-time weight stage into smem (permuted pairs, tf32 RNA) ----
    for (int i = tid; i < 16 * 512; i += 256) {
        int jj = i >> 9, k = i & 511, g = jj >> 2, cc = jj & 3;
        int pos = (k & ~7) + ((k & 3) << 1) + ((k >> 2) & 1);
        wsA[jj * 516 + pos] = to_tf32(Whh0[(size_t)(g * 512 + cbA + cc) * 512 + k]);
    }
    for (int i = tid; i < 16 * 256; i += 256) {
        int jj = i >> 8, k = i & 255, g = jj >> 2, cc = jj & 3;
        int pos = (k & ~7) + ((k & 3) << 1) + ((k >> 2) & 1);
        wsB[jj * 260 + pos] = to_tf32(WB[(size_t)(g * 256 + cbB + cc) * 256 + k]);
    }
    for (int i = tid; i < 1024; i += 256) csm[i] = 0.f;
    __syncthreads();

    // warp roles
    const bool isA = (w < 4);
    const int  wl  = isA ? w : w - 4;     // 0..3
    const int  KG  = isA ? 32 : 16;       // k16 groups
    const float* wsp = isA ? wsA : wsB;
    const int  wld = isA ? 516 : 260;
    float* gsp = isA ? gsA : gsB;
    const int  lbase4 = (isA ? 0 : lbaseB) >> 2;  // in float4

    const int b_e = tid & 127, top = tid >> 7;
    const int l4 = lane & 3, q = lane >> 2;

    for (int t = 0; t < TSTEPS; t++) {
        // ---- gx loads into registers (DRAM latency hides under mma) ----
        float4 gvA[2], gvB[2];
        {
            const size_t rowA = ((size_t)(b_e * TSTEPS + t)) << 11;
            const size_t rowB = ((size_t)(b_e * TSTEPS + t)) << 10;
            #pragma unroll
            for (int cp = 0; cp < 2; cp++) {
                const int g = top + cp * 2;
                gvA[cp] = *(const float4*)&g_gx0[rowA + g * 512 + cbA];
                gvB[cp] = *(const float4*)&gxB [rowB + g * 256 + cbB];
            }
        }

        float acc[2][2][4];
        if (t > 0) {
            #pragma unroll
            for (int m = 0; m < 2; m++)
                #pragma unroll
                for (int n = 0; n < 2; n++)
                    #pragma unroll
                    for (int e = 0; e < 4; e++) acc[m][n][e] = 0.f;

            const float4* hbp = (const float4*)(g_hb[(t - 1) & 1]) + lbase4;
            const int base0 = (wl * 2 + 0) * KG;
            const int base1 = (wl * 2 + 1) * KG;
            #pragma unroll 2
            for (int kg = 0; kg < KG; kg++) {
                const float4 a0l = __ldcg(hbp + (((base0 + kg) << 6) + lane));
                const float4 a0h = __ldcg(hbp + (((base0 + kg) << 6) + 32 + lane));
                const float4 a1l = __ldcg(hbp + (((base1 + kg) << 6) + lane));
                const float4 a1h = __ldcg(hbp + (((base1 + kg) << 6) + 32 + lane));
                #pragma unroll
                for (int nt = 0; nt < 2; nt++) {
                    const float2 b0 = *(const float2*)&wsp[(nt * 8 + q) * wld + (kg * 2 + 0) * 8 + l4 * 2];
                    const float2 b1 = *(const float2*)&wsp[(nt * 8 + q) * wld + (kg * 2 + 1) * 8 + l4 * 2];
                    mma8(acc[0][nt], a0l.x, a0h.x, a0l.y, a0h.y, b0.x, b0.y);
                    mma8(acc[0][nt], a0l.z, a0h.z, a0l.w, a0h.w, b1.x, b1.y);
                    mma8(acc[1][nt], a1l.x, a1h.x, a1l.y, a1h.y, b0.x, b0.y);
                    mma8(acc[1][nt], a1l.z, a1h.z, a1l.w, a1h.w, b1.x, b1.y);
                }
            }
        }

        // ---- stage gx into gate smem (disjoint ownership) ----
        #pragma unroll
        for (int cp = 0; cp < 2; cp++) {
            const int g = top + cp * 2;
            gsA[(g * 4 + 0) * 132 + b_e] = gvA[cp].x;
            gsA[(g * 4 + 1) * 132 + b_e] = gvA[cp].y;
            gsA[(g * 4 + 2) * 132 + b_e] = gvA[cp].z;
            gsA[(g * 4 + 3) * 132 + b_e] = gvA[cp].w;
            gsB[(g * 4 + 0) * 132 + b_e] = gvB[cp].x;
            gsB[(g * 4 + 1) * 132 + b_e] = gvB[cp].y;
            gsB[(g * 4 + 2) * 132 + b_e] = gvB[cp].z;
            gsB[(g * 4 + 3) * 132 + b_e] = gvB[cp].w;
        }
        __syncthreads();

        // ---- accumulate mma result into gate smem (disjoint per thread) ----
        if (t > 0) {
            #pragma unroll
            for (int m = 0; m < 2; m++) {
                const int r0 = wl * 32 + m * 16 + q;
                #pragma unroll
                for (int n = 0; n < 2; n++) {
                    const int c0 = n * 8 + l4 * 2;
                    gsp[ c0      * 132 + r0    ] += acc[m][n][0];
                    gsp[(c0 + 1) * 132 + r0    ] += acc[m][n][1];
                    gsp[ c0      * 132 + r0 + 8] += acc[m][n][2];
                    gsp[(c0 + 1) * 132 + r0 + 8] += acc[m][n][3];
                }
            }
        }
        __syncthreads();

        // ---- cell update + h stores ----
        float* hbw = g_hb[t & 1];
        #pragma unroll
        for (int u = 0; u < 2; u++) {
            float* gs = u ? gsB : gsA;
            const int cb     = u ? cbB : cbA;
            const int coloff = u ? coloffB : 0;
            const int lb     = u ? lbaseB : 0;
            const int KGu    = u ? 16 : 32;
            #pragma unroll
            for (int cp = 0; cp < 2; cp++) {
                const int cc = top * 2 + cp;
                const float gi = gs[( 0 + cc) * 132 + b_e];
                const float gf = gs[( 4 + cc) * 132 + b_e];
                const float gg = gs[( 8 + cc) * 132 + b_e];
                const float go = gs[(12 + cc) * 132 + b_e];
                const float cold = csm[(u * 4 + cc) * 128 + b_e];
                const float cn = sigf(gf) * cold + sigf(gi) * tanhf(gg);
                const float hn = sigf(go) * tanhf(cn);
                csm[(u * 4 + cc) * 128 + b_e] = cn;
                g_hcat[((size_t)(b_e * TSTEPS + t)) * 1024 + coloff + cb + cc] = hn;
                // fragment-layout tf32 store for next step's mma A operand
                const int col = cb + cc;
                const int kg = col >> 4, c16 = col & 15;
                const int blk = b_e >> 4, rl = b_e & 15;
                const int off = lb + ((blk * KGu + kg) << 8) + ((rl >> 3) << 7)
                              + (((rl & 7) * 4 + (c16 & 3)) << 2) + (c16 >> 2);
                hbw[off] = to_tf32(hn);
            }
        }

        // ---- grid barrier across the 128 resident CTAs ----
        if (t < TSTEPS - 1) {
            __threadfence();
            __syncthreads();
            if (tid == 0) {
                atomicAdd(&g_bar, 1u);
                const unsigned tgt = 128u * (unsigned)(t + 1);
                while (*(volatile unsigned*)&g_bar < tgt) __nanosleep(32);
                __threadfence();
            }
            __syncthreads();
        }
    }
}

// ------------------------------------------------------------------------------
// FC2 (7x256) + log_softmax, one warp per (b,t) row. (unchanged)
// ------------------------------------------------------------------------------
__global__ __launch_bounds__(256) void fc2_softmax(
    const float* __restrict__ W2, const float* __restrict__ b2,
    float* __restrict__ out)
{
    const int warp = threadIdx.x >> 5, lane = threadIdx.x & 31;
    const int row = blockIdx.x * 8 + warp;
    const float4* z4 = (const float4*)&g_z[(size_t)row * 256];
    const float4 z0 = z4[lane];
    const float4 z1 = z4[32 + lane];

    float logit[7];
    #pragma unroll
    for (int o = 0; o < 7; o++) {
        const float4* w4 = (const float4*)&W2[o * 256];
        const float4 w0 = w4[lane], w1 = w4[32 + lane];
        float p = z0.x * w0.x + z0.y * w0.y + z0.z * w0.z + z0.w * w0.w
                + z1.x * w1.x + z1.y * w1.y + z1.z * w1.z + z1.w * w1.w;
        #pragma unroll
        for (int s = 16; s > 0; s >>= 1) p += __shfl_xor_sync(0xffffffffu, p, s);
        logit[o] = p + b2[o];
    }
    float m = logit[0];
    #pragma unroll
    for (int o = 1; o < 7; o++) m = fmaxf(m, logit[o]);
    float se = 0.f;
    #pragma unroll
    for (int o = 0; o < 7; o++) se += expf(logit[o] - m);
    const float lse = logf(se);
    if (lane < 7) out[(size_t)row * 7 + lane] = logit[lane] - m - lse;
}

// ------------------------------------------------------------------------------
extern "C" void kernel_launch(void* const* d_in, const int* in_sizes, int n_in,
                              void* d_out, int out_size)
{
    const float* x0    = (const float*)d_in[0];
    const float* x1    = (const float*)d_in[1];
    const float* x2    = (const float*)d_in[2];
    const float* Wih0  = (const float*)d_in[3];
    const float* Whh0  = (const float*)d_in[4];
    const float* bih0  = (const float*)d_in[5];
    const float* bhh0  = (const float*)d_in[6];
    const float* Wih1  = (const float*)d_in[7];
    const float* Whh1  = (const float*)d_in[8];
    const float* bih1  = (const float*)d_in[9];
    const float* bhh1  = (const float*)d_in[10];
    const float* Wih2  = (const float*)d_in[11];
    const float* Whh2  = (const float*)d_in[12];
    const float* bih2  = (const float*)d_in[13];
    const float* bhh2  = (const float*)d_in[14];
    const float* fcW1  = (const float*)d_in[15];
    const float* fcb1  = (const float*)d_in[16];
    const float* fcW2  = (const float*)d_in[17];
    const float* fcb2  = (const float*)d_in[18];
    float* out = (float*)d_out;

    const int rec_smem = (16 * 516 + 16 * 260 + 16 * 132 * 2 + 2 * 4 * 128) * 4;
    cudaFuncSetAttribute(lstm_rec, cudaFuncAttributeMaxDynamicSharedMemorySize, rec_smem);

    reset_kernel<<<1, 1>>>();

    // input projections: gx = x @ W_ih^T + b_ih + b_hh
    { dim3 g(2048 / 64, BT / 64); gemm_xwt<<<g, 256>>>(x0, -1, Wih0, bih0, bhh0, 0, BT, 2048, 300, 0); }
    { dim3 g(1024 / 64, BT / 64); gemm_xwt<<<g, 256>>>(x1, -1, Wih1, bih1, bhh1, 1, BT, 1024,  74, 0); }
    { dim3 g(1024 / 64, BT / 64); gemm_xwt<<<g, 256>>>(x2, -1, Wih2, bih2, bhh2, 2, BT, 1024,  35, 0); }

    // persistent recurrence over T=256 (tensor-core tf32)
    lstm_rec<<<128, 256, rec_smem>>>(Whh0, Whh1, Whh2);

    // FC1 + ReLU: z = relu(hcat @ fc_W1^T + fc_b1)
    { dim3 g(256 / 64, BT / 64); gemm_xwt<<<g, 256>>>(nullptr, 0, fcW1, fcb1, nullptr, 3, BT, 256, 1024, 1); }

    // FC2 + log_softmax
    fc2_softmax<<<BT / 8, 256>>>(fcW2, fcb2, out);
}

// round 7
// speedup vs baseline: 2.3224x; 1.1060x over previous
#include <cuda_runtime.h>
#include <math.h>

// Problem constants
#define BATCH   128
#define TSTEPS  256
#define BT      32768          // BATCH*TSTEPS
#define HCAT    1024           // 512+256+256

// ---------------- scratch (device globals; no allocation allowed) -------------
__device__ float g_gx0[(size_t)BT * 2048];   // layer0 input proj (i,f,g,o)
__device__ float g_gx1[(size_t)BT * 1024];   // layer1
__device__ float g_gx2[(size_t)BT * 1024];   // layer2
__device__ float g_hcat[(size_t)BT * HCAT];  // hidden trajectories fp32, [b][t][1024]
__device__ float g_z[(size_t)BT * 256];      // FC1 output
__device__ float g_hb[2][131072];            // recurrent h, tf32, mma-fragment layout, double buffered
__device__ unsigned int g_flags[64];         // per-CTA barrier flags

__global__ void reset_kernel() { if (threadIdx.x < 64) g_flags[threadIdx.x] = 0u; }

// ------------------------------------------------------------------------------
// tf32 helpers
// ------------------------------------------------------------------------------
__device__ __forceinline__ float to_tf32(float x) {
    float r; asm("cvt.rna.tf32.f32 %0, %1;" : "=f"(r) : "f"(x)); return r;
}

__device__ __forceinline__ void mma8(float (&d)[4],
                                     float a0, float a1, float a2, float a3,
                                     float b0, float b1) {
    asm volatile("mma.sync.aligned.m16n8k8.row.col.f32.tf32.tf32.f32 "
                 "{%0,%1,%2,%3}, {%4,%5,%6,%7}, {%8,%9}, {%0,%1,%2,%3};"
                 : "+f"(d[0]), "+f"(d[1]), "+f"(d[2]), "+f"(d[3])
                 : "r"(__float_as_uint(a0)), "r"(__float_as_uint(a1)),
                   "r"(__float_as_uint(a2)), "r"(__float_as_uint(a3)),
                   "r"(__float_as_uint(b0)), "r"(__float_as_uint(b1)));
}

__device__ __forceinline__ float sigf(float x) { return 1.f / (1.f + expf(-x)); }

// ------------------------------------------------------------------------------
// tf32 tensor-core GEMM: C[M,N] = A[M,K] @ W[N,K]^T + b1 (+b2) (+relu)
// BM=128, BN=64, BK=16; 256 threads = 8 warps as 4(m) x 2(n); warp tile 32x32.
// ------------------------------------------------------------------------------
__global__ __launch_bounds__(256) void gemm_tf32(
    const float* __restrict__ Aext, int a_sel,
    const float* __restrict__ W,
    const float* __restrict__ b1, const float* __restrict__ b2,
    int c_sel, int M, int N, int K, int relu)
{
    __shared__ float As[16][136];   // stride 136 -> conflict-free fragment reads
    __shared__ float Ws[16][72];

    const float* A = (a_sel == 0) ? g_hcat : Aext;
    float* C;
    if      (c_sel == 0) C = g_gx0;
    else if (c_sel == 1) C = g_gx1;
    else if (c_sel == 2) C = g_gx2;
    else                 C = g_z;

    const int tid = threadIdx.x, lane = tid & 31, w = tid >> 5;
    const int wm = w >> 1, wn = w & 1;
    const int m0 = blockIdx.y * 128, n0 = blockIdx.x * 64;
    const int g = lane >> 2, c = lane & 3;

    float acc[2][4][4];
    #pragma unroll
    for (int mt = 0; mt < 2; mt++)
        #pragma unroll
        for (int nt = 0; nt < 4; nt++)
            #pragma unroll
            for (int e = 0; e < 4; e++) acc[mt][nt][e] = 0.f;

    const int ktiles = (K + 15) >> 4;
    const bool k4 = ((K & 3) == 0);

    for (int kt = 0; kt < ktiles; kt++) {
        const int kb = kt << 4;
        if (k4) {
            const int kq = (tid & 3) << 2, mi = tid >> 2;
            #pragma unroll
            for (int p = 0; p < 2; p++) {
                const int m = mi + p * 64;
                float4 v = make_float4(0.f, 0.f, 0.f, 0.f);
                if (kb + kq < K) v = *(const float4*)&A[(size_t)(m0 + m) * K + kb + kq];
                As[kq + 0][m] = to_tf32(v.x); As[kq + 1][m] = to_tf32(v.y);
                As[kq + 2][m] = to_tf32(v.z); As[kq + 3][m] = to_tf32(v.w);
            }
            {
                const int n = tid >> 2;
                float4 v = make_float4(0.f, 0.f, 0.f, 0.f);
                if (kb + kq < K) v = *(const float4*)&W[(size_t)(n0 + n) * K + kb + kq];
                Ws[kq + 0][n] = to_tf32(v.x); Ws[kq + 1][n] = to_tf32(v.y);
                Ws[kq + 2][n] = to_tf32(v.z); Ws[kq + 3][n] = to_tf32(v.w);
            }
        } else {
            const int k = tid & 15, mi = tid >> 4;
            #pragma unroll
            for (int p = 0; p < 8; p++) {
                const int m = mi + p * 16;
                const float v = (kb + k < K) ? A[(size_t)(m0 + m) * K + kb + k] : 0.f;
                As[k][m] = to_tf32(v);
            }
            #pragma unroll
            for (int p = 0; p < 4; p++) {
                const int n = mi + p * 16;
                const float v = (kb + k < K) ? W[(size_t)(n0 + n) * K + kb + k] : 0.f;
                Ws[k][n] = to_tf32(v);
            }
        }
        __syncthreads();

        #pragma unroll
        for (int ks = 0; ks < 16; ks += 8) {
            float a[2][4], b[4][2];
            #pragma unroll
            for (int mt = 0; mt < 2; mt++) {
                const int mr = wm * 32 + mt * 16 + g;
                a[mt][0] = As[ks + c][mr];
                a[mt][1] = As[ks + c][mr + 8];
                a[mt][2] = As[ks + c + 4][mr];
                a[mt][3] = As[ks + c + 4][mr + 8];
            }
            #pragma unroll
            for (int nt = 0; nt < 4; nt++) {
                const int nc = wn * 32 + nt * 8 + g;
                b[nt][0] = Ws[ks + c][nc];
                b[nt][1] = Ws[ks + c + 4][nc];
            }
            #pragma unroll
            for (int mt = 0; mt < 2; mt++)
                #pragma unroll
                for (int nt = 0; nt < 4; nt++)
                    mma8(acc[mt][nt], a[mt][0], a[mt][1], a[mt][2], a[mt][3],
                         b[nt][0], b[nt][1]);
        }
        __syncthreads();
    }

    #pragma unroll
    for (int mt = 0; mt < 2; mt++) {
        #pragma unroll
        for (int nt = 0; nt < 4; nt++) {
            const int nc = n0 + wn * 32 + nt * 8 + c * 2;
            float bb0 = b1[nc], bb1 = b1[nc + 1];
            if (b2) { bb0 += b2[nc]; bb1 += b2[nc + 1]; }
            #pragma unroll
            for (int hf = 0; hf < 2; hf++) {
                const int mr = m0 + wm * 32 + mt * 16 + g + hf * 8;
                float v0 = acc[mt][nt][hf * 2 + 0] + bb0;
                float v1 = acc[mt][nt][hf * 2 + 1] + bb1;
                if (relu) { v0 = fmaxf(v0, 0.f); v1 = fmaxf(v1, 0.f); }
                float2 st = make_float2(v0, v1);
                *(float2*)&C[(size_t)mr * N + nc] = st;
            }
        }
    }
}

// ------------------------------------------------------------------------------
// Recurrence mma inner loop: 4-deep register-ring prefetch of A fragments.
// ------------------------------------------------------------------------------
template<int KG>
__device__ __forceinline__ void rec_mma(
    float (&acc)[2][4][4], const float4* __restrict__ hbp,
    int base0, int base1, int lane,
    const float* __restrict__ wsp, int wld, int q, int l4)
{
    float4 A0l[4], A0h[4], A1l[4], A1h[4];
    #pragma unroll
    for (int p = 0; p < 4; p++) {
        A0l[p] = __ldcg(hbp + (((base0 + p) << 6) + lane));
        A0h[p] = __ldcg(hbp + (((base0 + p) << 6) + 32 + lane));
        A1l[p] = __ldcg(hbp + (((base1 + p) << 6) + lane));
        A1h[p] = __ldcg(hbp + (((base1 + p) << 6) + 32 + lane));
    }
    #pragma unroll
    for (int kg = 0; kg < KG; kg++) {
        const int s = kg & 3;
        const float4 a0l = A0l[s], a0h = A0h[s];
        const float4 a1l = A1l[s], a1h = A1h[s];
        if (kg + 4 < KG) {
            A0l[s] = __ldcg(hbp + (((base0 + kg + 4) << 6) + lane));
            A0h[s] = __ldcg(hbp + (((base0 + kg + 4) << 6) + 32 + lane));
            A1l[s] = __ldcg(hbp + (((base1 + kg + 4) << 6) + lane));
            A1h[s] = __ldcg(hbp + (((base1 + kg + 4) << 6) + 32 + lane));
        }
        #pragma unroll
        for (int nt = 0; nt < 4; nt++) {
            const float2 b0 = *(const float2*)&wsp[(nt * 8 + q) * wld + (kg * 2 + 0) * 8 + l4 * 2];
            const float2 b1 = *(const float2*)&wsp[(nt * 8 + q) * wld + (kg * 2 + 1) * 8 + l4 * 2];
            mma8(acc[0][nt], a0l.x, a0h.x, a0l.y, a0h.y, b0.x, b0.y);
            mma8(acc[0][nt], a0l.z, a0h.z, a0l.w, a0h.w, b1.x, b1.y);
            mma8(acc[1][nt], a1l.x, a1h.x, a1l.y, a1h.y, b0.x, b0.y);
            mma8(acc[1][nt], a1l.z, a1h.z, a1l.w, a1h.w, b1.x, b1.y);
        }
    }
}

// ------------------------------------------------------------------------------
// Persistent LSTM recurrence: 64 CTAs x 256 threads, flag-array grid barrier.
// CTA owns 8 cells of layer0 (unit A, warps 0-3) and 8 cells of layer1/2
// (unit B, warps 4-7). Warp = 32 batch rows x 32 gate cols.
// Weights resident in smem (tf32, fragment-pair permuted) for all 256 steps.
// ------------------------------------------------------------------------------
__global__ void __launch_bounds__(256, 1) lstm_rec(
    const float* __restrict__ Whh0,
    const float* __restrict__ Whh1,
    const float* __restrict__ Whh2)
{
    extern __shared__ float sm[];
    float* wsA = sm;                       // [32][516]
    float* wsB = wsA + 32 * 516;           // [32][260]
    float* gsA = wsB + 32 * 260;           // [32][132]
    float* gsB = gsA + 32 * 132;           // [32][132]
    float* csm = gsB + 32 * 132;           // [2][8][128]

    const int cta = blockIdx.x, tid = threadIdx.x;
    const int lane = tid & 31, w = tid >> 5;
    const int cbA = cta * 8;

    const float* WB; const float* gxB; int coloffB, cbB, lbaseB;
    if (cta < 32) { WB = Whh1; gxB = g_gx1; coloffB = 512; cbB = cta * 8;        lbaseB = 65536; }
    else          { WB = Whh2; gxB = g_gx2; coloffB = 768; cbB = (cta - 32) * 8; lbaseB = 98304; }

    // ---- one-time weight stage (fragment-pair permute, tf32 RNA) ----
    for (int i = tid; i < 32 * 512; i += 256) {
        int jj = i >> 9, k = i & 511, g = jj >> 3, cc = jj & 7;
        int pos = (k & ~7) + ((k & 3) << 1) + ((k >> 2) & 1);
        wsA[jj * 516 + pos] = to_tf32(Whh0[(size_t)(g * 512 + cbA + cc) * 512 + k]);
    }
    for (int i = tid; i < 32 * 256; i += 256) {
        int jj = i >> 8, k = i & 255, g = jj >> 3, cc = jj & 7;
        int pos = (k & ~7) + ((k & 3) << 1) + ((k >> 2) & 1);
        wsB[jj * 260 + pos] = to_tf32(WB[(size_t)(g * 256 + cbB + cc) * 256 + k]);
    }
    for (int i = tid; i < 2 * 8 * 128; i += 256) csm[i] = 0.f;
    __syncthreads();

    const bool isA = (w < 4);
    const int  wl  = isA ? w : w - 4;
    const float* wsp = isA ? wsA : wsB;
    const int  wld = isA ? 516 : 260;
    float* gsp = isA ? gsA : gsB;
    const int  lbase4 = (isA ? 0 : lbaseB) >> 2;   // float4 units

    const int b_e = tid & 127, top = tid >> 7;
    const int l4 = lane & 3, q = lane >> 2;

    for (int t = 0; t < TSTEPS; t++) {
        // ---- gx loads into registers (latency hidden under mma) ----
        float4 gvA[2][2], gvB[2][2];
        {
            const size_t rowA = ((size_t)(b_e * TSTEPS + t)) << 11;
            const size_t rowB = ((size_t)(b_e * TSTEPS + t)) << 10;
            #pragma unroll
            for (int cp = 0; cp < 2; cp++) {
                const int g = top + cp * 2;
                gvA[cp][0] = *(const float4*)&g_gx0[rowA + g * 512 + cbA];
                gvA[cp][1] = *(const float4*)&g_gx0[rowA + g * 512 + cbA + 4];
                gvB[cp][0] = *(const float4*)&gxB [rowB + g * 256 + cbB];
                gvB[cp][1] = *(const float4*)&gxB [rowB + g * 256 + cbB + 4];
            }
        }

        float acc[2][4][4];
        if (t > 0) {
            #pragma unroll
            for (int m = 0; m < 2; m++)
                #pragma unroll
                for (int nt = 0; nt < 4; nt++)
                    #pragma unroll
                    for (int e = 0; e < 4; e++) acc[m][nt][e] = 0.f;

            const float4* hbp = (const float4*)(g_hb[(t - 1) & 1]) + lbase4;
            if (isA) rec_mma<32>(acc, hbp, (wl * 2 + 0) * 32, (wl * 2 + 1) * 32, lane, wsp, wld, q, l4);
            else     rec_mma<16>(acc, hbp, (wl * 2 + 0) * 16, (wl * 2 + 1) * 16, lane, wsp, wld, q, l4);
        }

        // ---- stage gx into gate smem (disjoint ownership) ----
        #pragma unroll
        for (int cp = 0; cp < 2; cp++) {
            const int g = top + cp * 2;
            #pragma unroll
            for (int h4 = 0; h4 < 2; h4++) {
                const float4 va = gvA[cp][h4];
                const float4 vb = gvB[cp][h4];
                const int base = g * 8 + h4 * 4;
                gsA[(base + 0) * 132 + b_e] = va.x;
                gsA[(base + 1) * 132 + b_e] = va.y;
                gsA[(base + 2) * 132 + b_e] = va.z;
                gsA[(base + 3) * 132 + b_e] = va.w;
                gsB[(base + 0) * 132 + b_e] = vb.x;
                gsB[(base + 1) * 132 + b_e] = vb.y;
                gsB[(base + 2) * 132 + b_e] = vb.z;
                gsB[(base + 3) * 132 + b_e] = vb.w;
            }
        }
        __syncthreads();

        // ---- accumulate mma into gate smem (disjoint per thread) ----
        if (t > 0) {
            #pragma unroll
            for (int m = 0; m < 2; m++) {
                const int r0 = wl * 32 + m * 16 + q;
                #pragma unroll
                for (int nt = 0; nt < 4; nt++) {
                    const int c0 = nt * 8 + l4 * 2;
                    gsp[ c0      * 132 + r0    ] += acc[m][nt][0];
                    gsp[(c0 + 1) * 132 + r0    ] += acc[m][nt][1];
                    gsp[ c0      * 132 + r0 + 8] += acc[m][nt][2];
                    gsp[(c0 + 1) * 132 + r0 + 8] += acc[m][nt][3];
                }
            }
        }
        __syncthreads();

        // ---- cell update + h stores ----
        float* hbw = g_hb[t & 1];
        #pragma unroll
        for (int u = 0; u < 2; u++) {
            float* gs = u ? gsB : gsA;
            const int cb     = u ? cbB : cbA;
            const int coloff = u ? coloffB : 0;
            const int lb     = u ? lbaseB : 0;
            const int KGu    = u ? 16 : 32;
            #pragma unroll
            for (int cp = 0; cp < 4; cp++) {
                const int cc = top * 4 + cp;
                const float gi = gs[( 0 + cc) * 132 + b_e];
                const float gf = gs[( 8 + cc) * 132 + b_e];
                const float gg = gs[(16 + cc) * 132 + b_e];
                const float go = gs[(24 + cc) * 132 + b_e];
                const float cold = csm[(u * 8 + cc) * 128 + b_e];
                const float cn = sigf(gf) * cold + sigf(gi) * tanhf(gg);
                const float hn = sigf(go) * tanhf(cn);
                csm[(u * 8 + cc) * 128 + b_e] = cn;
                g_hcat[((size_t)(b_e * TSTEPS + t)) * 1024 + coloff + cb + cc] = hn;
                // fragment-layout tf32 store for next step's mma A operand
                const int col = cb + cc;
                const int kg = col >> 4, c16 = col & 15;
                const int blk = b_e >> 4, rl = b_e & 15;
                const int off = lb + ((blk * KGu + kg) << 8) + ((rl >> 3) << 7)
                              + (((rl & 7) * 4 + (c16 & 3)) << 2) + (c16 >> 2);
                hbw[off] = to_tf32(hn);
            }
        }

        // ---- flag-array grid barrier across the 64 resident CTAs ----
        if (t < TSTEPS - 1) {
            __threadfence();
            __syncthreads();
            if (tid == 0) *((volatile unsigned*)&g_flags[cta]) = (unsigned)(t + 1);
            if (tid < 64) {
                while (*((volatile unsigned*)&g_flags[tid]) < (unsigned)(t + 1)) __nanosleep(16);
                __threadfence();
            }
            __syncthreads();
        }
    }
}

// ------------------------------------------------------------------------------
// FC2 (7x256) + log_softmax, one warp per (b,t) row.
// ------------------------------------------------------------------------------
__global__ __launch_bounds__(256) void fc2_softmax(
    const float* __restrict__ W2, const float* __restrict__ b2,
    float* __restrict__ out)
{
    const int warp = threadIdx.x >> 5, lane = threadIdx.x & 31;
    const int row = blockIdx.x * 8 + warp;
    const float4* z4 = (const float4*)&g_z[(size_t)row * 256];
    const float4 z0 = z4[lane];
    const float4 z1 = z4[32 + lane];

    float logit[7];
    #pragma unroll
    for (int o = 0; o < 7; o++) {
        const float4* w4 = (const float4*)&W2[o * 256];
        const float4 w0 = w4[lane], w1 = w4[32 + lane];
        float p = z0.x * w0.x + z0.y * w0.y + z0.z * w0.z + z0.w * w0.w
                + z1.x * w1.x + z1.y * w1.y + z1.z * w1.z + z1.w * w1.w;
        #pragma unroll
        for (int s = 16; s > 0; s >>= 1) p += __shfl_xor_sync(0xffffffffu, p, s);
        logit[o] = p + b2[o];
    }
    float m = logit[0];
    #pragma unroll
    for (int o = 1; o < 7; o++) m = fmaxf(m, logit[o]);
    float se = 0.f;
    #pragma unroll
    for (int o = 0; o < 7; o++) se += expf(logit[o] - m);
    const float lse = logf(se);
    if (lane < 7) out[(size_t)row * 7 + lane] = logit[lane] - m - lse;
}

// ------------------------------------------------------------------------------
extern "C" void kernel_launch(void* const* d_in, const int* in_sizes, int n_in,
                              void* d_out, int out_size)
{
    const float* x0    = (const float*)d_in[0];
    const float* x1    = (const float*)d_in[1];
    const float* x2    = (const float*)d_in[2];
    const float* Wih0  = (const float*)d_in[3];
    const float* Whh0  = (const float*)d_in[4];
    const float* bih0  = (const float*)d_in[5];
    const float* bhh0  = (const float*)d_in[6];
    const float* Wih1  = (const float*)d_in[7];
    const float* Whh1  = (const float*)d_in[8];
    const float* bih1  = (const float*)d_in[9];
    const float* bhh1  = (const float*)d_in[10];
    const float* Wih2  = (const float*)d_in[11];
    const float* Whh2  = (const float*)d_in[12];
    const float* bih2  = (const float*)d_in[13];
    const float* bhh2  = (const float*)d_in[14];
    const float* fcW1  = (const float*)d_in[15];
    const float* fcb1  = (const float*)d_in[16];
    const float* fcW2  = (const float*)d_in[17];
    const float* fcb2  = (const float*)d_in[18];
    float* out = (float*)d_out;

    const int rec_smem = (32 * 516 + 32 * 260 + 32 * 132 * 2 + 2 * 8 * 128) * 4;
    cudaFuncSetAttribute(lstm_rec, cudaFuncAttributeMaxDynamicSharedMemorySize, rec_smem);

    reset_kernel<<<1, 64>>>();

    // input projections: gx = x @ W_ih^T + b_ih + b_hh   (tf32 mma)
    { dim3 g(2048 / 64, BT / 128); gemm_tf32<<<g, 256>>>(x0, -1, Wih0, bih0, bhh0, 0, BT, 2048, 300, 0); }
    { dim3 g(1024 / 64, BT / 128); gemm_tf32<<<g, 256>>>(x1, -1, Wih1, bih1, bhh1, 1, BT, 1024,  74, 0); }
    { dim3 g(1024 / 64, BT / 128); gemm_tf32<<<g, 256>>>(x2, -1, Wih2, bih2, bhh2, 2, BT, 1024,  35, 0); }

    // persistent recurrence over T=256 (tensor-core tf32, 64 CTAs)
    lstm_rec<<<64, 256, rec_smem>>>(Whh0, Whh1, Whh2);

    // FC1 + ReLU: z = relu(hcat @ fc_W1^T + fc_b1)
    { dim3 g(256 / 64, BT / 128); gemm_tf32<<<g, 256>>>(nullptr, 0, fcW1, fcb1, nullptr, 3, BT, 256, 1024, 1); }

    // FC2 + log_softmax
    fc2_softmax<<<BT / 8, 256>>>(fcW2, fcb2, out);
}

// round 10
// speedup vs baseline: 2.7855x; 1.1994x over previous
#include <cuda_runtime.h>
#include <cuda_bf16.h>
#include <math.h>

// Problem constants
#define BATCH   128
#define TSTEPS  256
#define BT      32768          // BATCH*TSTEPS
#define HCAT    1024           // 512+256+256

typedef unsigned int uint;

// ---------------- scratch (device globals; no allocation allowed) -------------
__device__ float g_gx0[(size_t)BT * 2048];   // layer0 input proj (i,f,g,o)
__device__ float g_gx1[(size_t)BT * 1024];   // layer1
__device__ float g_gx2[(size_t)BT * 1024];   // layer2
__device__ float g_hcat[(size_t)BT * HCAT];  // hidden trajectories fp32, [b][t][1024]
__device__ float g_z[(size_t)BT * 256];      // FC1 output
__device__ __nv_bfloat16 g_hb[2][131072];    // recurrent h, bf16 mma-fragment layout, dbl buf
__device__ unsigned int g_flags[128];        // per-CTA barrier flags

__global__ void reset_kernel() { if (threadIdx.x < 128) g_flags[threadIdx.x] = 0u; }

// ------------------------------------------------------------------------------
// helpers
// ------------------------------------------------------------------------------
__device__ __forceinline__ float to_tf32(float x) {
    float r; asm("cvt.rna.tf32.f32 %0, %1;" : "=f"(r) : "f"(x)); return r;
}

__device__ __forceinline__ void mma8(float (&d)[4],
                                     float a0, float a1, float a2, float a3,
                                     float b0, float b1) {
    asm volatile("mma.sync.aligned.m16n8k8.row.col.f32.tf32.tf32.f32 "
                 "{%0,%1,%2,%3}, {%4,%5,%6,%7}, {%8,%9}, {%0,%1,%2,%3};"
                 : "+f"(d[0]), "+f"(d[1]), "+f"(d[2]), "+f"(d[3])
                 : "r"(__float_as_uint(a0)), "r"(__float_as_uint(a1)),
                   "r"(__float_as_uint(a2)), "r"(__float_as_uint(a3)),
                   "r"(__float_as_uint(b0)), "r"(__float_as_uint(b1)));
}

// bf16 m16n8k16 mma, fp32 accum
__device__ __forceinline__ void mma16(float (&d)[4], uint4 a, uint b0, uint b1) {
    asm volatile("mma.sync.aligned.m16n8k16.row.col.f32.bf16.bf16.f32 "
                 "{%0,%1,%2,%3}, {%4,%5,%6,%7}, {%8,%9}, {%0,%1,%2,%3};"
                 : "+f"(d[0]), "+f"(d[1]), "+f"(d[2]), "+f"(d[3])
                 : "r"(a.x), "r"(a.y), "r"(a.z), "r"(a.w), "r"(b0), "r"(b1));
}

__device__ __forceinline__ uint pack_bf16x2(float lo, float hi) {
    __nv_bfloat162 t = __floats2bfloat162_rn(lo, hi);
    return *(uint*)&t;
}

__device__ __forceinline__ float sigf(float x) { return 1.f / (1.f + __expf(-x)); }
__device__ __forceinline__ float tanhfast(float x) {
    const float e = __expf(-2.f * fabsf(x));
    const float r = (1.f - e) / (1.f + e);
    return copysignf(r, x);
}

// ------------------------------------------------------------------------------
// tf32 tensor-core GEMM: C[M,N] = A[M,K] @ W[N,K]^T + b1 (+b2) (+relu)
// BM=128, BN=64, BK=16; 256 threads = 8 warps as 4(m) x 2(n); warp tile 32x32.
// ------------------------------------------------------------------------------
__global__ __launch_bounds__(256) void gemm_tf32(
    const float* __restrict__ Aext, int a_sel,
    const float* __restrict__ W,
    const float* __restrict__ b1, const float* __restrict__ b2,
    int c_sel, int M, int N, int K, int relu)
{
    __shared__ float As[16][136];
    __shared__ float Ws[16][72];

    const float* A = (a_sel == 0) ? g_hcat : Aext;
    float* C;
    if      (c_sel == 0) C = g_gx0;
    else if (c_sel == 1) C = g_gx1;
    else if (c_sel == 2) C = g_gx2;
    else                 C = g_z;

    const int tid = threadIdx.x, lane = tid & 31, w = tid >> 5;
    const int wm = w >> 1, wn = w & 1;
    const int m0 = blockIdx.y * 128, n0 = blockIdx.x * 64;
    const int g = lane >> 2, c = lane & 3;

    float acc[2][4][4];
    #pragma unroll
    for (int mt = 0; mt < 2; mt++)
        #pragma unroll
        for (int nt = 0; nt < 4; nt++)
            #pragma unroll
            for (int e = 0; e < 4; e++) acc[mt][nt][e] = 0.f;

    const int ktiles = (K + 15) >> 4;
    const bool k4 = ((K & 3) == 0);

    for (int kt = 0; kt < ktiles; kt++) {
        const int kb = kt << 4;
        if (k4) {
            const int kq = (tid & 3) << 2, mi = tid >> 2;
            #pragma unroll
            for (int p = 0; p < 2; p++) {
                const int m = mi + p * 64;
                float4 v = make_float4(0.f, 0.f, 0.f, 0.f);
                if (kb + kq < K) v = *(const float4*)&A[(size_t)(m0 + m) * K + kb + kq];
                As[kq + 0][m] = to_tf32(v.x); As[kq + 1][m] = to_tf32(v.y);
                As[kq + 2][m] = to_tf32(v.z); As[kq + 3][m] = to_tf32(v.w);
            }
            {
                const int n = tid >> 2;
                float4 v = make_float4(0.f, 0.f, 0.f, 0.f);
                if (kb + kq < K) v = *(const float4*)&W[(size_t)(n0 + n) * K + kb + kq];
                Ws[kq + 0][n] = to_tf32(v.x); Ws[kq + 1][n] = to_tf32(v.y);
                Ws[kq + 2][n] = to_tf32(v.z); Ws[kq + 3][n] = to_tf32(v.w);
            }
        } else {
            const int k = tid & 15, mi = tid >> 4;
            #pragma unroll
            for (int p = 0; p < 8; p++) {
                const int m = mi + p * 16;
                const float v = (kb + k < K) ? A[(size_t)(m0 + m) * K + kb + k] : 0.f;
                As[k][m] = to_tf32(v);
            }
            #pragma unroll
            for (int p = 0; p < 4; p++) {
                const int n = mi + p * 16;
                const float v = (kb + k < K) ? W[(size_t)(n0 + n) * K + kb + k] : 0.f;
                Ws[k][n] = to_tf32(v);
            }
        }
        __syncthreads();

        #pragma unroll
        for (int ks = 0; ks < 16; ks += 8) {
            float a[2][4], b[4][2];
            #pragma unroll
            for (int mt = 0; mt < 2; mt++) {
                const int mr = wm * 32 + mt * 16 + g;
                a[mt][0] = As[ks + c][mr];
                a[mt][1] = As[ks + c][mr + 8];
                a[mt][2] = As[ks + c + 4][mr];
                a[mt][3] = As[ks + c + 4][mr + 8];
            }
            #pragma unroll
            for (int nt = 0; nt < 4; nt++) {
                const int nc = wn * 32 + nt * 8 + g;
                b[nt][0] = Ws[ks + c][nc];
                b[nt][1] = Ws[ks + c + 4][nc];
            }
            #pragma unroll
            for (int mt = 0; mt < 2; mt++)
                #pragma unroll
                for (int nt = 0; nt < 4; nt++)
                    mma8(acc[mt][nt], a[mt][0], a[mt][1], a[mt][2], a[mt][3],
                         b[nt][0], b[nt][1]);
        }
        __syncthreads();
    }

    #pragma unroll
    for (int mt = 0; mt < 2; mt++) {
        #pragma unroll
        for (int nt = 0; nt < 4; nt++) {
            const int nc = n0 + wn * 32 + nt * 8 + c * 2;
            float bb0 = b1[nc], bb1 = b1[nc + 1];
            if (b2) { bb0 += b2[nc]; bb1 += b2[nc + 1]; }
            #pragma unroll
            for (int hf = 0; hf < 2; hf++) {
                const int mr = m0 + wm * 32 + mt * 16 + g + hf * 8;
                float v0 = acc[mt][nt][hf * 2 + 0] + bb0;
                float v1 = acc[mt][nt][hf * 2 + 1] + bb1;
                if (relu) { v0 = fmaxf(v0, 0.f); v1 = fmaxf(v1, 0.f); }
                float2 st = make_float2(v0, v1);
                *(float2*)&C[(size_t)mr * N + nc] = st;
            }
        }
    }
}

// ------------------------------------------------------------------------------
// Recurrence bf16 mma inner loop; 4-deep register-ring prefetch (8 LDG.128).
// hbp: uint4 pointer at this layer's base of g_hb[(t-1)&1].
// tb0/tb1: tile indices (blk*KG) for the warp's two 16-row m-tiles.
// ------------------------------------------------------------------------------
template<int KG>
__device__ __forceinline__ void rec_mma(
    float (&acc)[2][2][4], const uint4* __restrict__ hbp,
    int tb0, int tb1, int lane,
    const uint* __restrict__ wsp, int wld, int g, int c)
{
    uint4 R0[4], R1[4];
    #pragma unroll
    for (int p = 0; p < 4; p++) {
        R0[p] = __ldcg(hbp + (tb0 + p) * 32 + lane);
        R1[p] = __ldcg(hbp + (tb1 + p) * 32 + lane);
    }
    #pragma unroll
    for (int kg = 0; kg < KG; kg++) {
        const int s = kg & 3;
        const uint4 a0 = R0[s], a1 = R1[s];
        if (kg + 4 < KG) {
            R0[s] = __ldcg(hbp + (tb0 + kg + 4) * 32 + lane);
            R1[s] = __ldcg(hbp + (tb1 + kg + 4) * 32 + lane);
        }
        #pragma unroll
        for (int nt = 0; nt < 2; nt++) {
            const uint b0 = wsp[(nt * 8 + g) * wld + kg * 8 + c];
            const uint b1 = wsp[(nt * 8 + g) * wld + kg * 8 + 4 + c];
            mma16(acc[0][nt], a0, b0, b1);
            mma16(acc[1][nt], a1, b0, b1);
        }
    }
}

// ------------------------------------------------------------------------------
// Persistent LSTM recurrence (bf16 tensor cores). 128 CTAs x 256 threads.
// CTA owns 4 cells of layer0 (unit A, warps 0-3) and 4 cells of layer1/2
// (unit B, warps 4-7). Warp = 32 batch rows x 16 gate cols.
// Weights resident in smem as packed bf16x2 B-fragments for all 256 steps.
// h: fp32 -> g_hcat; bf16 fragment layout -> g_hb[t&1].
//
// g_hb layout: per layer, tiles of (16 batch x 16 cell), tile = blk*KG + kg,
// 256 bf16 each; lane l holds its 8 bf16 (a0..a3) contiguously at l*8.
// ------------------------------------------------------------------------------
__global__ void __launch_bounds__(256, 1) lstm_rec(
    const float* __restrict__ Whh0,
    const float* __restrict__ Whh1,
    const float* __restrict__ Whh2)
{
    extern __shared__ uint smu[];
    uint*  wsA = smu;                       // [16][260]  bf16x2 words, pad -> 4g+c banks
    uint*  wsB = wsA + 16 * 260;            // [16][132]
    float* gsA = (float*)(wsB + 16 * 132);  // [16][132] gate preacts fp32
    float* gsB = gsA + 16 * 132;            // [16][132]
    float* csm = gsB + 16 * 132;            // [2][4][128] cell state

    const int cta = blockIdx.x, tid = threadIdx.x;
    const int lane = tid & 31, w = tid >> 5;
    const int cbA = cta * 4;

    const float* WB; const float* gxB; int coloffB, cbB, lbB_elem, lbB_u4;
    if (cta < 64) { WB = Whh1; gxB = g_gx1; coloffB = 512; cbB = cta * 4;        lbB_elem = 65536; lbB_u4 = 8192; }
    else          { WB = Whh2; gxB = g_gx2; coloffB = 768; cbB = (cta - 64) * 4; lbB_elem = 98304; lbB_u4 = 12288; }

    // ---- one-time weight stage: pack bf16x2 B-fragment words ----
    for (int i = tid; i < 16 * 256; i += 256) {
        const int jj = i >> 8, ww = i & 255;
        const int kg = ww >> 3, sub = ww & 7;
        const int k = kg * 16 + (sub >> 2) * 8 + (sub & 3) * 2;
        const float* row = &Whh0[(size_t)((jj >> 2) * 512 + cbA + (jj & 3)) * 512];
        wsA[jj * 260 + ww] = pack_bf16x2(row[k], row[k + 1]);
    }
    for (int i = tid; i < 16 * 128; i += 256) {
        const int jj = i >> 7, ww = i & 127;
        const int kg = ww >> 3, sub = ww & 7;
        const int k = kg * 16 + (sub >> 2) * 8 + (sub & 3) * 2;
        const float* row = &WB[(size_t)((jj >> 2) * 256 + cbB + (jj & 3)) * 256];
        wsB[jj * 132 + ww] = pack_bf16x2(row[k], row[k + 1]);
    }
    for (int i = tid; i < 2 * 4 * 128; i += 256) csm[i] = 0.f;
    __syncthreads();

    const bool isA = (w < 4);
    const int  wl  = isA ? w : w - 4;
    const uint* wsp = isA ? wsA : wsB;
    const int  wld = isA ? 260 : 132;
    float* gsp = isA ? gsA : gsB;
    const int  KGw = isA ? 32 : 16;
    const int  lw_u4 = isA ? 0 : lbB_u4;

    const int b_e = tid & 127, top = tid >> 7;
    const int g = lane >> 2, c = lane & 3;

    for (int t = 0; t < TSTEPS; t++) {
        // ---- gx loads into registers ----
        float4 gvA[2], gvB[2];
        {
            const size_t rowA = ((size_t)(b_e * TSTEPS + t)) << 11;
            const size_t rowB = ((size_t)(b_e * TSTEPS + t)) << 10;
            #pragma unroll
            for (int cp = 0; cp < 2; cp++) {
                const int gg = top + cp * 2;
                gvA[cp] = *(const float4*)&g_gx0[rowA + gg * 512 + cbA];
                gvB[cp] = *(const float4*)&gxB [rowB + gg * 256 + cbB];
            }
        }

        float acc[2][2][4];
        if (t > 0) {
            #pragma unroll
            for (int m = 0; m < 2; m++)
                #pragma unroll
                for (int nt = 0; nt < 2; nt++)
                    #pragma unroll
                    for (int e = 0; e < 4; e++) acc[m][nt][e] = 0.f;

            const uint4* hbp = (const uint4*)(g_hb[(t - 1) & 1]) + lw_u4;
            if (isA) rec_mma<32>(acc, hbp, (wl * 2 + 0) * 32, (wl * 2 + 1) * 32, lane, wsp, wld, g, c);
            else     rec_mma<16>(acc, hbp, (wl * 2 + 0) * 16, (wl * 2 + 1) * 16, lane, wsp, wld, g, c);
        }

        // ---- stage gx into gate smem (disjoint ownership) ----
        #pragma unroll
        for (int cp = 0; cp < 2; cp++) {
            const int gg = top + cp * 2;
            gsA[(gg * 4 + 0) * 132 + b_e] = gvA[cp].x;
            gsA[(gg * 4 + 1) * 132 + b_e] = gvA[cp].y;
            gsA[(gg * 4 + 2) * 132 + b_e] = gvA[cp].z;
            gsA[(gg * 4 + 3) * 132 + b_e] = gvA[cp].w;
            gsB[(gg * 4 + 0) * 132 + b_e] = gvB[cp].x;
            gsB[(gg * 4 + 1) * 132 + b_e] = gvB[cp].y;
            gsB[(gg * 4 + 2) * 132 + b_e] = gvB[cp].z;
            gsB[(gg * 4 + 3) * 132 + b_e] = gvB[cp].w;
        }
        __syncthreads();

        // ---- accumulate mma into gate smem (disjoint per thread) ----
        if (t > 0) {
            #pragma unroll
            for (int m = 0; m < 2; m++) {
                const int r0 = wl * 32 + m * 16 + g;
                #pragma unroll
                for (int nt = 0; nt < 2; nt++) {
                    const int c0 = nt * 8 + c * 2;
                    gsp[ c0      * 132 + r0    ] += acc[m][nt][0];
                    gsp[(c0 + 1) * 132 + r0    ] += acc[m][nt][1];
                    gsp[ c0      * 132 + r0 + 8] += acc[m][nt][2];
                    gsp[(c0 + 1) * 132 + r0 + 8] += acc[m][nt][3];
                }
            }
        }
        __syncthreads();

        // ---- cell update + h stores ----
        __nv_bfloat16* hbw = g_hb[t & 1];
        #pragma unroll
        for (int u = 0; u < 2; u++) {
            float* gs = u ? gsB : gsA;
            const int cb     = u ? cbB : cbA;
            const int coloff = u ? coloffB : 0;
            const int lbE    = u ? lbB_elem : 0;
            const int KGu    = u ? 16 : 32;
            #pragma unroll
            for (int cp = 0; cp < 2; cp++) {
                const int cc = top * 2 + cp;
                const float gi = gs[( 0 + cc) * 132 + b_e];
                const float gf = gs[( 4 + cc) * 132 + b_e];
                const float gg = gs[( 8 + cc) * 132 + b_e];
                const float go = gs[(12 + cc) * 132 + b_e];
                const float cold = csm[(u * 4 + cc) * 128 + b_e];
                const float cn = sigf(gf) * cold + sigf(gi) * tanhfast(gg);
                const float hn = sigf(go) * tanhfast(cn);
                csm[(u * 4 + cc) * 128 + b_e] = cn;
                g_hcat[((size_t)(b_e * TSTEPS + t)) * 1024 + coloff + cb + cc] = hn;
                // bf16 fragment-layout store for next step's mma A operand
                const int col = cb + cc;
                const int kg = col >> 4, c16 = col & 15;
                const int blk = b_e >> 4, rl = b_e & 15;
                const int lane_w = (rl & 7) * 4 + ((c16 & 7) >> 1);
                const int reg = (rl >> 3) + 2 * (c16 >> 3);
                const int off = lbE + (blk * KGu + kg) * 256 + lane_w * 8 + reg * 2 + (c16 & 1);
                hbw[off] = __float2bfloat16(hn);
            }
        }

        // ---- flag-array grid barrier across the 128 resident CTAs ----
        if (t < TSTEPS - 1) {
            __threadfence();
            __syncthreads();
            if (tid == 0) *((volatile unsigned*)&g_flags[cta]) = (unsigned)(t + 1);
            if (tid < 128) {
                while (*((volatile unsigned*)&g_flags[tid]) < (unsigned)(t + 1)) __nanosleep(16);
                __threadfence();
            }
            __syncthreads();
        }
    }
}

// ------------------------------------------------------------------------------
// FC2 (7x256) + log_softmax, one warp per (b,t) row.
// ------------------------------------------------------------------------------
__global__ __launch_bounds__(256) void fc2_softmax(
    const float* __restrict__ W2, const float* __restrict__ b2,
    float* __restrict__ out)
{
    const int warp = threadIdx.x >> 5, lane = threadIdx.x & 31;
    const int row = blockIdx.x * 8 + warp;
    const float4* z4 = (const float4*)&g_z[(size_t)row * 256];
    const float4 z0 = z4[lane];
    const float4 z1 = z4[32 + lane];

    float logit[7];
    #pragma unroll
    for (int o = 0; o < 7; o++) {
        const float4* w4 = (const float4*)&W2[o * 256];
        const float4 w0 = w4[lane], w1 = w4[32 + lane];
        float p = z0.x * w0.x + z0.y * w0.y + z0.z * w0.z + z0.w * w0.w
                + z1.x * w1.x + z1.y * w1.y + z1.z * w1.z + z1.w * w1.w;
        #pragma unroll
        for (int s = 16; s > 0; s >>= 1) p += __shfl_xor_sync(0xffffffffu, p, s);
        logit[o] = p + b2[o];
    }
    float m = logit[0];
    #pragma unroll
    for (int o = 1; o < 7; o++) m = fmaxf(m, logit[o]);
    float se = 0.f;
    #pragma unroll
    for (int o = 0; o < 7; o++) se += expf(logit[o] - m);
    const float lse = logf(se);
    if (lane < 7) out[(size_t)row * 7 + lane] = logit[lane] - m - lse;
}

// ------------------------------------------------------------------------------
extern "C" void kernel_launch(void* const* d_in, const int* in_sizes, int n_in,
                              void* d_out, int out_size)
{
    const float* x0    = (const float*)d_in[0];
    const float* x1    = (const float*)d_in[1];
    const float* x2    = (const float*)d_in[2];
    const float* Wih0  = (const float*)d_in[3];
    const float* Whh0  = (const float*)d_in[4];
    const float* bih0  = (const float*)d_in[5];
    const float* bhh0  = (const float*)d_in[6];
    const float* Wih1  = (const float*)d_in[7];
    const float* Whh1  = (const float*)d_in[8];
    const float* bih1  = (const float*)d_in[9];
    const float* bhh1  = (const float*)d_in[10];
    const float* Wih2  = (const float*)d_in[11];
    const float* Whh2  = (const float*)d_in[12];
    const float* bih2  = (const float*)d_in[13];
    const float* bhh2  = (const float*)d_in[14];
    const float* fcW1  = (const float*)d_in[15];
    const float* fcb1  = (const float*)d_in[16];
    const float* fcW2  = (const float*)d_in[17];
    const float* fcb2  = (const float*)d_in[18];
    float* out = (float*)d_out;

    const int rec_smem = (16 * 260 + 16 * 132 + 2 * 16 * 132 + 2 * 4 * 128) * 4;
    cudaFuncSetAttribute(lstm_rec, cudaFuncAttributeMaxDynamicSharedMemorySize, rec_smem);

    reset_kernel<<<1, 128>>>();

    // input projections: gx = x @ W_ih^T + b_ih + b_hh   (tf32 mma)
    { dim3 g(2048 / 64, BT / 128); gemm_tf32<<<g, 256>>>(x0, -1, Wih0, bih0, bhh0, 0, BT, 2048, 300, 0); }
    { dim3 g(1024 / 64, BT / 128); gemm_tf32<<<g, 256>>>(x1, -1, Wih1, bih1, bhh1, 1, BT, 1024,  74, 0); }
    { dim3 g(1024 / 64, BT / 128); gemm_tf32<<<g, 256>>>(x2, -1, Wih2, bih2, bhh2, 2, BT, 1024,  35, 0); }

    // persistent recurrence over T=256 (bf16 tensor cores, 128 CTAs)
    lstm_rec<<<128, 256, rec_smem>>>(Whh0, Whh1, Whh2);

    // FC1 + ReLU: z = relu(hcat @ fc_W1^T + fc_b1)
    { dim3 g(256 / 64, BT / 128); gemm_tf32<<<g, 256>>>(nullptr, 0, fcW1, fcb1, nullptr, 3, BT, 256, 1024, 1); }

    // FC2 + log_softmax
    fc2_softmax<<<BT / 8, 256>>>(fcW2, fcb2, out);
}

// round 14
// speedup vs baseline: 3.7209x; 1.3358x over previous
#include <cuda_runtime.h>
#include <cuda_bf16.h>
#include <math.h>

// Problem constants
#define BATCH   128
#define TSTEPS  256
#define BT      32768          // BATCH*TSTEPS
#define HCAT    1024           // 512+256+256

typedef unsigned int uint;

// ---------------- scratch (device globals; no allocation allowed) -------------
__device__ float g_gx0[(size_t)BT * 2048];   // layer0 input proj (i,f,g,o)
__device__ float g_gx1[(size_t)BT * 1024];   // layer1
__device__ float g_gx2[(size_t)BT * 1024];   // layer2
__device__ float g_hcat[(size_t)BT * HCAT];  // hidden trajectories fp32, [b][t][1024]
__device__ float g_z[(size_t)BT * 256];      // FC1 output
__device__ __nv_bfloat16 g_hb[2][131072];    // recurrent h, bf16 mma-fragment layout, dbl buf
__device__ unsigned int g_flags[128];        // per-CTA barrier flags

__global__ void reset_kernel() { if (threadIdx.x < 128) g_flags[threadIdx.x] = 0u; }

// ------------------------------------------------------------------------------
// helpers
// ------------------------------------------------------------------------------
__device__ __forceinline__ float to_tf32(float x) {
    float r; asm("cvt.rna.tf32.f32 %0, %1;" : "=f"(r) : "f"(x)); return r;
}

__device__ __forceinline__ void mma8(float (&d)[4],
                                     float a0, float a1, float a2, float a3,
                                     float b0, float b1) {
    asm volatile("mma.sync.aligned.m16n8k8.row.col.f32.tf32.tf32.f32 "
                 "{%0,%1,%2,%3}, {%4,%5,%6,%7}, {%8,%9}, {%0,%1,%2,%3};"
                 : "+f"(d[0]), "+f"(d[1]), "+f"(d[2]), "+f"(d[3])
                 : "r"(__float_as_uint(a0)), "r"(__float_as_uint(a1)),
                   "r"(__float_as_uint(a2)), "r"(__float_as_uint(a3)),
                   "r"(__float_as_uint(b0)), "r"(__float_as_uint(b1)));
}

// bf16 m16n8k16 mma, fp32 accum
__device__ __forceinline__ void mma16(float (&d)[4], uint4 a, uint b0, uint b1) {
    asm volatile("mma.sync.aligned.m16n8k16.row.col.f32.bf16.bf16.f32 "
                 "{%0,%1,%2,%3}, {%4,%5,%6,%7}, {%8,%9}, {%0,%1,%2,%3};"
                 : "+f"(d[0]), "+f"(d[1]), "+f"(d[2]), "+f"(d[3])
                 : "r"(a.x), "r"(a.y), "r"(a.z), "r"(a.w), "r"(b0), "r"(b1));
}

__device__ __forceinline__ uint pack_bf16x2(float lo, float hi) {
    __nv_bfloat162 t = __floats2bfloat162_rn(lo, hi);
    return *(uint*)&t;
}

__device__ __forceinline__ float sigf(float x) { return 1.f / (1.f + __expf(-x)); }
__device__ __forceinline__ float tanhfast(float x) {
    const float e = __expf(-2.f * fabsf(x));
    const float r = (1.f - e) / (1.f + e);
    return copysignf(r, x);
}

__device__ __forceinline__ void cpa16(void* dst, const void* src, int srcbytes) {
    unsigned d = (unsigned)__cvta_generic_to_shared(dst);
    asm volatile("cp.async.ca.shared.global [%0], [%1], 16, %2;"
                 :: "r"(d), "l"(src), "r"(srcbytes));
}

// ------------------------------------------------------------------------------
// tf32 tensor-core GEMM: C[M,N] = A[M,K] @ W[N,K]^T + b1 (+b2) (+relu)
// BM=128, BN=64, BK=16; 256 threads = 8 warps (4m x 2n), warp tile 32x32.
// K%4==0 path: 3-stage cp.async pipeline, compute-then-issue, one sync/tile:
//   wait_group(1) -> __syncthreads -> compute(buf kt%3) -> issue tile kt+2.
// The R11/R12 2-stage version computed right after its own wait_group with NO
// barrier, racing other warps' in-flight copies (root cause of the 1e-2 error).
// Fragments tf32-RNA-converted in registers (RZ truncation is biased and
// compounds through the LSTM recurrence).
// ------------------------------------------------------------------------------
__device__ __forceinline__ void gemm_compute(
    const float (*As)[20], const float (*Ws)[20],
    float (&acc)[2][4][4], int wm, int wn, int g, int c)
{
    #pragma unroll
    for (int ks = 0; ks < 16; ks += 8) {
        float a[2][4], b[4][2];
        #pragma unroll
        for (int mt = 0; mt < 2; mt++) {
            const int mr = wm * 32 + mt * 16 + g;
            a[mt][0] = to_tf32(As[mr][ks + c]);
            a[mt][1] = to_tf32(As[mr + 8][ks + c]);
            a[mt][2] = to_tf32(As[mr][ks + c + 4]);
            a[mt][3] = to_tf32(As[mr + 8][ks + c + 4]);
        }
        #pragma unroll
        for (int nt = 0; nt < 4; nt++) {
            const int nc = wn * 32 + nt * 8 + g;
            b[nt][0] = to_tf32(Ws[nc][ks + c]);
            b[nt][1] = to_tf32(Ws[nc][ks + c + 4]);
        }
        #pragma unroll
        for (int mt = 0; mt < 2; mt++)
            #pragma unroll
            for (int nt = 0; nt < 4; nt++)
                mma8(acc[mt][nt], a[mt][0], a[mt][1], a[mt][2], a[mt][3],
                     b[nt][0], b[nt][1]);
    }
}

__device__ __forceinline__ int clamp16(int bytes) {
    return bytes < 0 ? 0 : (bytes > 16 ? 16 : bytes);
}

__global__ __launch_bounds__(256, 2) void gemm_tf32(
    const float* __restrict__ Aext, int a_sel,
    const float* __restrict__ W,
    const float* __restrict__ b1, const float* __restrict__ b2,
    int c_sel, int M, int N, int K, int relu)
{
    __shared__ float As[3][128][20];
    __shared__ float Ws[3][64][20];

    const float* A = (a_sel == 0) ? g_hcat : Aext;
    float* C;
    if      (c_sel == 0) C = g_gx0;
    else if (c_sel == 1) C = g_gx1;
    else if (c_sel == 2) C = g_gx2;
    else                 C = g_z;

    const int tid = threadIdx.x, lane = tid & 31, w = tid >> 5;
    const int wm = w >> 1, wn = w & 1;
    const int m0 = blockIdx.y * 128, n0 = blockIdx.x * 64;
    const int g = lane >> 2, c = lane & 3;

    float acc[2][4][4];
    #pragma unroll
    for (int mt = 0; mt < 2; mt++)
        #pragma unroll
        for (int nt = 0; nt < 4; nt++)
            #pragma unroll
            for (int e = 0; e < 4; e++) acc[mt][nt][e] = 0.f;

    const int ktiles = (K + 15) >> 4;

    if ((K & 3) == 0) {
        // ---- 3-stage cp.async pipeline ----
        const int arow = tid >> 1, akq = (tid & 1) * 8;       // A: 2 chunks/thread
        const int wrow = tid >> 2, wkq = (tid & 3) * 4;       // W: 1 chunk/thread

        auto issue_tile = [&](int kt) {
            const int kb = kt << 4;
            const int bf = kt % 3;
            const float* s0 = &A[(size_t)(m0 + arow) * K + kb + akq];
            const int r0 = clamp16((K - kb - akq) * 4);
            const int r1 = clamp16((K - kb - akq - 4) * 4);
            cpa16(&As[bf][arow][akq], r0 ? s0 : A, r0);
            cpa16(&As[bf][arow][akq + 4], r1 ? s0 + 4 : A, r1);
            const float* sw = &W[(size_t)(n0 + wrow) * K + kb + wkq];
            const int rw = clamp16((K - kb - wkq) * 4);
            cpa16(&Ws[bf][wrow][wkq], rw ? sw : W, rw);
            asm volatile("cp.async.commit_group;");
        };

        issue_tile(0);
        if (ktiles > 1) issue_tile(1);

        for (int kt = 0; kt < ktiles; kt++) {
            if (kt + 1 < ktiles) { asm volatile("cp.async.wait_group 1;"); }
            else                 { asm volatile("cp.async.wait_group 0;"); }
            __syncthreads();   // everyone's tile-kt copies visible; prior reads of
                               // buf (kt+2)%3 (= compute kt-1) are globally done
            gemm_compute(As[kt % 3], Ws[kt % 3], acc, wm, wn, g, c);
            if (kt + 2 < ktiles) issue_tile(kt + 2);
        }
    } else {
        // ---- generic path (small K: 74, 35) ----
        const int k = tid & 15, mi = tid >> 4;
        for (int kt = 0; kt < ktiles; kt++) {
            const int kb = kt << 4;
            #pragma unroll
            for (int p = 0; p < 8; p++) {
                const int m = mi + p * 16;
                As[0][m][k] = (kb + k < K) ? A[(size_t)(m0 + m) * K + kb + k] : 0.f;
            }
            #pragma unroll
            for (int p = 0; p < 4; p++) {
                const int n = mi + p * 16;
                Ws[0][n][k] = (kb + k < K) ? W[(size_t)(n0 + n) * K + kb + k] : 0.f;
            }
            __syncthreads();
            gemm_compute(As[0], Ws[0], acc, wm, wn, g, c);
            __syncthreads();
        }
    }

    #pragma unroll
    for (int mt = 0; mt < 2; mt++) {
        #pragma unroll
        for (int nt = 0; nt < 4; nt++) {
            const int nc = n0 + wn * 32 + nt * 8 + c * 2;
            float bb0 = b1[nc], bb1 = b1[nc + 1];
            if (b2) { bb0 += b2[nc]; bb1 += b2[nc + 1]; }
            #pragma unroll
            for (int hf = 0; hf < 2; hf++) {
                const int mr = m0 + wm * 32 + mt * 16 + g + hf * 8;
                float v0 = acc[mt][nt][hf * 2 + 0] + bb0;
                float v1 = acc[mt][nt][hf * 2 + 1] + bb1;
                if (relu) { v0 = fmaxf(v0, 0.f); v1 = fmaxf(v1, 0.f); }
                float2 st = make_float2(v0, v1);
                *(float2*)&C[(size_t)mr * N + nc] = st;
            }
        }
    }
}

// ------------------------------------------------------------------------------
// Recurrence bf16 mma inner loop; 4-deep register-ring prefetch (8 LDG.128).
// ------------------------------------------------------------------------------
template<int KG>
__device__ __forceinline__ void rec_mma(
    float (&acc)[2][2][4], const uint4* __restrict__ hbp,
    int tb0, int tb1, int lane,
    const uint* __restrict__ wsp, int wld, int g, int c)
{
    uint4 R0[4], R1[4];
    #pragma unroll
    for (int p = 0; p < 4; p++) {
        R0[p] = __ldcg(hbp + (tb0 + p) * 32 + lane);
        R1[p] = __ldcg(hbp + (tb1 + p) * 32 + lane);
    }
    #pragma unroll
    for (int kg = 0; kg < KG; kg++) {
        const int s = kg & 3;
        const uint4 a0 = R0[s], a1 = R1[s];
        if (kg + 4 < KG) {
            R0[s] = __ldcg(hbp + (tb0 + kg + 4) * 32 + lane);
            R1[s] = __ldcg(hbp + (tb1 + kg + 4) * 32 + lane);
        }
        #pragma unroll
        for (int nt = 0; nt < 2; nt++) {
            const uint b0 = wsp[(nt * 8 + g) * wld + kg * 8 + c];
            const uint b1 = wsp[(nt * 8 + g) * wld + kg * 8 + 4 + c];
            mma16(acc[0][nt], a0, b0, b1);
            mma16(acc[1][nt], a1, b0, b1);
        }
    }
}

// ------------------------------------------------------------------------------
// Persistent LSTM recurrence (bf16 tensor cores). 128 CTAs x 256 threads.
// CTA owns 4 cells of layer0 (unit A, warps 0-3) and 4 cells of layer1/2
// (unit B, warps 4-7). Cell state in registers; release/acquire grid barrier;
// coalesced float4 g_hcat writes via smem transpose.
// ------------------------------------------------------------------------------
__global__ void __launch_bounds__(256, 1) lstm_rec(
    const float* __restrict__ Whh0,
    const float* __restrict__ Whh1,
    const float* __restrict__ Whh2)
{
    extern __shared__ uint smu[];
    uint*  wsA = smu;                        // [16][260]  bf16x2 B-fragment words
    uint*  wsB = wsA + 16 * 260;             // [16][132]
    float* gsA = (float*)(wsB + 16 * 132);   // [16][132] gate preacts fp32
    float* gsB = gsA + 16 * 132;             // [16][132]
    float* hstage = gsB + 16 * 132;          // [8][132]  h values for coalesced hcat write

    const int cta = blockIdx.x, tid = threadIdx.x;
    const int lane = tid & 31, w = tid >> 5;
    const int cbA = cta * 4;

    const float* WB; const float* gxB; int coloffB, cbB, lbB_elem, lbB_u4;
    if (cta < 64) { WB = Whh1; gxB = g_gx1; coloffB = 512; cbB = cta * 4;        lbB_elem = 65536; lbB_u4 = 8192; }
    else          { WB = Whh2; gxB = g_gx2; coloffB = 768; cbB = (cta - 64) * 4; lbB_elem = 98304; lbB_u4 = 12288; }

    // ---- one-time weight stage: pack bf16x2 B-fragment words ----
    for (int i = tid; i < 16 * 256; i += 256) {
        const int jj = i >> 8, ww = i & 255;
        const int kg = ww >> 3, sub = ww & 7;
        const int k = kg * 16 + (sub >> 2) * 8 + (sub & 3) * 2;
        const float* row = &Whh0[(size_t)((jj >> 2) * 512 + cbA + (jj & 3)) * 512];
        wsA[jj * 260 + ww] = pack_bf16x2(row[k], row[k + 1]);
    }
    for (int i = tid; i < 16 * 128; i += 256) {
        const int jj = i >> 7, ww = i & 127;
        const int kg = ww >> 3, sub = ww & 7;
        const int k = kg * 16 + (sub >> 2) * 8 + (sub & 3) * 2;
        const float* row = &WB[(size_t)((jj >> 2) * 256 + cbB + (jj & 3)) * 256];
        wsB[jj * 132 + ww] = pack_bf16x2(row[k], row[k + 1]);
    }
    __syncthreads();

    const bool isA = (w < 4);
    const int  wl  = isA ? w : w - 4;
    const uint* wsp = isA ? wsA : wsB;
    const int  wld = isA ? 260 : 132;
    float* gsp = isA ? gsA : gsB;
    const int  lw_u4 = isA ? 0 : lbB_u4;

    const int b_e = tid & 127, top = tid >> 7;
    const int g = lane >> 2, c = lane & 3;

    float creg[2][2] = {{0.f, 0.f}, {0.f, 0.f}};   // cell state in registers

    for (int t = 0; t < TSTEPS; t++) {
        // ---- gx loads into registers ----
        float4 gvA[2], gvB[2];
        {
            const size_t rowA = ((size_t)(b_e * TSTEPS + t)) << 11;
            const size_t rowB = ((size_t)(b_e * TSTEPS + t)) << 10;
            #pragma unroll
            for (int cp = 0; cp < 2; cp++) {
                const int gg = top + cp * 2;
                gvA[cp] = *(const float4*)&g_gx0[rowA + gg * 512 + cbA];
                gvB[cp] = *(const float4*)&gxB [rowB + gg * 256 + cbB];
            }
        }

        float acc[2][2][4];
        if (t > 0) {
            #pragma unroll
            for (int m = 0; m < 2; m++)
                #pragma unroll
                for (int nt = 0; nt < 2; nt++)
                    #pragma unroll
                    for (int e = 0; e < 4; e++) acc[m][nt][e] = 0.f;

            const uint4* hbp = (const uint4*)(g_hb[(t - 1) & 1]) + lw_u4;
            if (isA) rec_mma<32>(acc, hbp, (wl * 2 + 0) * 32, (wl * 2 + 1) * 32, lane, wsp, wld, g, c);
            else     rec_mma<16>(acc, hbp, (wl * 2 + 0) * 16, (wl * 2 + 1) * 16, lane, wsp, wld, g, c);
        }

        // ---- stage gx into gate smem (disjoint ownership) ----
        #pragma unroll
        for (int cp = 0; cp < 2; cp++) {
            const int gg = top + cp * 2;
            gsA[(gg * 4 + 0) * 132 + b_e] = gvA[cp].x;
            gsA[(gg * 4 + 1) * 132 + b_e] = gvA[cp].y;
            gsA[(gg * 4 + 2) * 132 + b_e] = gvA[cp].z;
            gsA[(gg * 4 + 3) * 132 + b_e] = gvA[cp].w;
            gsB[(gg * 4 + 0) * 132 + b_e] = gvB[cp].x;
            gsB[(gg * 4 + 1) * 132 + b_e] = gvB[cp].y;
            gsB[(gg * 4 + 2) * 132 + b_e] = gvB[cp].z;
            gsB[(gg * 4 + 3) * 132 + b_e] = gvB[cp].w;
        }
        __syncthreads();

        // ---- accumulate mma into gate smem (disjoint per thread) ----
        if (t > 0) {
            #pragma unroll
            for (int m = 0; m < 2; m++) {
                const int r0 = wl * 32 + m * 16 + g;
                #pragma unroll
                for (int nt = 0; nt < 2; nt++) {
                    const int c0 = nt * 8 + c * 2;
                    gsp[ c0      * 132 + r0    ] += acc[m][nt][0];
                    gsp[(c0 + 1) * 132 + r0    ] += acc[m][nt][1];
                    gsp[ c0      * 132 + r0 + 8] += acc[m][nt][2];
                    gsp[(c0 + 1) * 132 + r0 + 8] += acc[m][nt][3];
                }
            }
        }
        __syncthreads();

        // ---- cell update + h stores (c in registers) ----
        __nv_bfloat16* hbw = g_hb[t & 1];
        #pragma unroll
        for (int u = 0; u < 2; u++) {
            float* gs = u ? gsB : gsA;
            const int cb  = u ? cbB : cbA;
            const int lbE = u ? lbB_elem : 0;
            const int KGu = u ? 16 : 32;
            #pragma unroll
            for (int cp = 0; cp < 2; cp++) {
                const int cc = top * 2 + cp;
                const float gi = gs[( 0 + cc) * 132 + b_e];
                const float gf = gs[( 4 + cc) * 132 + b_e];
                const float gg = gs[( 8 + cc) * 132 + b_e];
                const float go = gs[(12 + cc) * 132 + b_e];
                const float cold = creg[u][cp];
                const float cn = sigf(gf) * cold + sigf(gi) * tanhfast(gg);
                const float hn = sigf(go) * tanhfast(cn);
                creg[u][cp] = cn;
                hstage[(u * 4 + cc) * 132 + b_e] = hn;
                // bf16 fragment-layout store for next step's mma A operand
                const int col = cb + cc;
                const int kg = col >> 4, c16 = col & 15;
                const int blk = b_e >> 4, rl = b_e & 15;
                const int lane_w = (rl & 7) * 4 + ((c16 & 7) >> 1);
                const int reg = (rl >> 3) + 2 * (c16 >> 3);
                const int off = lbE + (blk * KGu + kg) * 256 + lane_w * 8 + reg * 2 + (c16 & 1);
                hbw[off] = __float2bfloat16(hn);
            }
        }
        __syncthreads();   // hstage ready; all g_hb stores issued

        // ---- release barrier signal early (orders g_hb stores, CG pattern) ----
        if (t < TSTEPS - 1 && tid == 0) {
            asm volatile("st.release.gpu.u32 [%0], %1;"
                         :: "l"(g_flags + cta), "r"((unsigned)(t + 1)) : "memory");
        }

        // ---- coalesced float4 g_hcat write (not ordered by barrier; FC1-only) ----
        {
            const int uu = top;
            const int cb  = uu ? cbB : cbA;
            const int col = uu ? coloffB : 0;
            float4 hv;
            hv.x = hstage[(uu * 4 + 0) * 132 + b_e];
            hv.y = hstage[(uu * 4 + 1) * 132 + b_e];
            hv.z = hstage[(uu * 4 + 2) * 132 + b_e];
            hv.w = hstage[(uu * 4 + 3) * 132 + b_e];
            *(float4*)&g_hcat[((size_t)(b_e * TSTEPS + t)) * 1024 + col + cb] = hv;
        }

        // ---- acquire-poll across the 128 resident CTAs ----
        if (t < TSTEPS - 1) {
            if (tid < 128) {
                unsigned v;
                while (true) {
                    asm volatile("ld.acquire.gpu.u32 %0, [%1];"
                                 : "=r"(v) : "l"(g_flags + tid) : "memory");
                    if (v >= (unsigned)(t + 1)) break;
                    __nanosleep(16);
                }
            }
            __syncthreads();
        }
    }
}

// ------------------------------------------------------------------------------
// FC2 (7x256) + log_softmax, one warp per (b,t) row.
// ------------------------------------------------------------------------------
__global__ __launch_bounds__(256) void fc2_softmax(
    const float* __restrict__ W2, const float* __restrict__ b2,
    float* __restrict__ out)
{
    const int warp = threadIdx.x >> 5, lane = threadIdx.x & 31;
    const int row = blockIdx.x * 8 + warp;
    const float4* z4 = (const float4*)&g_z[(size_t)row * 256];
    const float4 z0 = z4[lane];
    const float4 z1 = z4[32 + lane];

    float logit[7];
    #pragma unroll
    for (int o = 0; o < 7; o++) {
        const float4* w4 = (const float4*)&W2[o * 256];
        const float4 w0 = w4[lane], w1 = w4[32 + lane];
        float p = z0.x * w0.x + z0.y * w0.y + z0.z * w0.z + z0.w * w0.w
                + z1.x * w1.x + z1.y * w1.y + z1.z * w1.z + z1.w * w1.w;
        #pragma unroll
        for (int s = 16; s > 0; s >>= 1) p += __shfl_xor_sync(0xffffffffu, p, s);
        logit[o] = p + b2[o];
    }
    float m = logit[0];
    #pragma unroll
    for (int o = 1; o < 7; o++) m = fmaxf(m, logit[o]);
    float se = 0.f;
    #pragma unroll
    for (int o = 0; o < 7; o++) se += expf(logit[o] - m);
    const float lse = logf(se);
    if (lane < 7) out[(size_t)row * 7 + lane] = logit[lane] - m - lse;
}

// ------------------------------------------------------------------------------
extern "C" void kernel_launch(void* const* d_in, const int* in_sizes, int n_in,
                              void* d_out, int out_size)
{
    const float* x0    = (const float*)d_in[0];
    const float* x1    = (const float*)d_in[1];
    const float* x2    = (const float*)d_in[2];
    const float* Wih0  = (const float*)d_in[3];
    const float* Whh0  = (const float*)d_in[4];
    const float* bih0  = (const float*)d_in[5];
    const float* bhh0  = (const float*)d_in[6];
    const float* Wih1  = (const float*)d_in[7];
    const float* Whh1  = (const float*)d_in[8];
    const float* bih1  = (const float*)d_in[9];
    const float* bhh1  = (const float*)d_in[10];
    const float* Wih2  = (const float*)d_in[11];
    const float* Whh2  = (const float*)d_in[12];
    const float* bih2  = (const float*)d_in[13];
    const float* bhh2  = (const float*)d_in[14];
    const float* fcW1  = (const float*)d_in[15];
    const float* fcb1  = (const float*)d_in[16];
    const float* fcW2  = (const float*)d_in[17];
    const float* fcb2  = (const float*)d_in[18];
    float* out = (float*)d_out;

    const int rec_smem = (16 * 260 + 16 * 132 + 2 * 16 * 132 + 8 * 132) * 4;
    cudaFuncSetAttribute(lstm_rec, cudaFuncAttributeMaxDynamicSharedMemorySize, rec_smem);

    reset_kernel<<<1, 128>>>();

    // input projections: gx = x @ W_ih^T + b_ih + b_hh   (tf32 mma, cp.async pipe)
    { dim3 g(2048 / 64, BT / 128); gemm_tf32<<<g, 256>>>(x0, -1, Wih0, bih0, bhh0, 0, BT, 2048, 300, 0); }
    { dim3 g(1024 / 64, BT / 128); gemm_tf32<<<g, 256>>>(x1, -1, Wih1, bih1, bhh1, 1, BT, 1024,  74, 0); }
    { dim3 g(1024 / 64, BT / 128); gemm_tf32<<<g, 256>>>(x2, -1, Wih2, bih2, bhh2, 2, BT, 1024,  35, 0); }

    // persistent recurrence over T=256 (bf16 tensor cores, 128 CTAs)
    lstm_rec<<<128, 256, rec_smem>>>(Whh0, Whh1, Whh2);

    // FC1 + ReLU: z = relu(hcat @ fc_W1^T + fc_b1)
    { dim3 g(256 / 64, BT / 128); gemm_tf32<<<g, 256>>>(nullptr, 0, fcW1, fcb1, nullptr, 3, BT, 256, 1024, 1); }

    // FC2 + log_softmax
    fc2_softmax<<<BT / 8, 256>>>(fcW2, fcb2, out);
}

// round 15
// speedup vs baseline: 4.0025x; 1.0757x over previous
#include <cuda_runtime.h>
#include <cuda_bf16.h>
#include <math.h>

// Problem constants
#define BATCH   128
#define TSTEPS  256
#define BT      32768          // BATCH*TSTEPS
#define HCAT    1024           // 512+256+256

typedef unsigned int uint;

// ---------------- scratch (device globals; no allocation allowed) -------------
__device__ float g_gx0[(size_t)BT * 2048];   // layer0 input proj (i,f,g,o)
__device__ float g_gx1[(size_t)BT * 1024];   // layer1
__device__ float g_gx2[(size_t)BT * 1024];   // layer2
__device__ float g_hcat[(size_t)BT * HCAT];  // hidden trajectories fp32, [b][t][1024]
__device__ float g_z[(size_t)BT * 256];      // FC1 output
__device__ __nv_bfloat16 g_hb[2][131072];    // recurrent h, bf16 mma-fragment layout, dbl buf
__device__ unsigned int g_flags[128];        // per-CTA barrier flags

__global__ void reset_kernel() { if (threadIdx.x < 128) g_flags[threadIdx.x] = 0u; }

// ------------------------------------------------------------------------------
// helpers
// ------------------------------------------------------------------------------
// bf16 m16n8k16 mma, fp32 accum
__device__ __forceinline__ void mma16(float (&d)[4], uint4 a, uint b0, uint b1) {
    asm volatile("mma.sync.aligned.m16n8k16.row.col.f32.bf16.bf16.f32 "
                 "{%0,%1,%2,%3}, {%4,%5,%6,%7}, {%8,%9}, {%0,%1,%2,%3};"
                 : "+f"(d[0]), "+f"(d[1]), "+f"(d[2]), "+f"(d[3])
                 : "r"(a.x), "r"(a.y), "r"(a.z), "r"(a.w), "r"(b0), "r"(b1));
}

__device__ __forceinline__ uint pack_bf16x2(float lo, float hi) {
    __nv_bfloat162 t = __floats2bfloat162_rn(lo, hi);
    return *(uint*)&t;
}

__device__ __forceinline__ float sigf(float x) { return 1.f / (1.f + __expf(-x)); }
__device__ __forceinline__ float tanhfast(float x) {
    const float e = __expf(-2.f * fabsf(x));
    const float r = (1.f - e) / (1.f + e);
    return copysignf(r, x);
}

__device__ __forceinline__ void cpa16(void* dst, const void* src, int srcbytes) {
    unsigned d = (unsigned)__cvta_generic_to_shared(dst);
    asm volatile("cp.async.ca.shared.global [%0], [%1], 16, %2;"
                 :: "r"(d), "l"(src), "r"(srcbytes));
}

// ------------------------------------------------------------------------------
// bf16 tensor-core GEMM: C[M,N] = A[M,K] @ W[N,K]^T + b1 (+b2) (+relu)
// BM=128, BN=64, BK=16; 256 threads = 8 warps (4m x 2n), warp tile 32x32.
// fp32 in smem; fragments converted to packed bf16x2 in registers (RN,
// zero-mean). Per k16 tile: 16 packs + 8 mma16 (vs tf32: 32 cvt + 16 mma8).
// K%4==0 path: 3-stage cp.async pipeline, compute-then-issue, one sync/tile.
// ------------------------------------------------------------------------------
__device__ __forceinline__ void gemm_compute(
    const float (*As)[20], const float (*Ws)[20],
    float (&acc)[2][4][4], int wm, int wn, int g, int c)
{
    uint4 a[2]; uint b[4][2];
    #pragma unroll
    for (int mt = 0; mt < 2; mt++) {
        const int mr = wm * 32 + mt * 16 + g;
        a[mt].x = pack_bf16x2(As[mr    ][c * 2    ], As[mr    ][c * 2 + 1]);
        a[mt].y = pack_bf16x2(As[mr + 8][c * 2    ], As[mr + 8][c * 2 + 1]);
        a[mt].z = pack_bf16x2(As[mr    ][c * 2 + 8], As[mr    ][c * 2 + 9]);
        a[mt].w = pack_bf16x2(As[mr + 8][c * 2 + 8], As[mr + 8][c * 2 + 9]);
    }
    #pragma unroll
    for (int nt = 0; nt < 4; nt++) {
        const int nc = wn * 32 + nt * 8 + g;
        b[nt][0] = pack_bf16x2(Ws[nc][c * 2    ], Ws[nc][c * 2 + 1]);
        b[nt][1] = pack_bf16x2(Ws[nc][c * 2 + 8], Ws[nc][c * 2 + 9]);
    }
    #pragma unroll
    for (int mt = 0; mt < 2; mt++)
        #pragma unroll
        for (int nt = 0; nt < 4; nt++)
            mma16(acc[mt][nt], a[mt], b[nt][0], b[nt][1]);
}

__device__ __forceinline__ int clamp16(int bytes) {
    return bytes < 0 ? 0 : (bytes > 16 ? 16 : bytes);
}

__global__ __launch_bounds__(256, 2) void gemm_bf16(
    const float* __restrict__ Aext, int a_sel,
    const float* __restrict__ W,
    const float* __restrict__ b1, const float* __restrict__ b2,
    int c_sel, int M, int N, int K, int relu)
{
    __shared__ float As[3][128][20];
    __shared__ float Ws[3][64][20];

    const float* A = (a_sel == 0) ? g_hcat : Aext;
    float* C;
    if      (c_sel == 0) C = g_gx0;
    else if (c_sel == 1) C = g_gx1;
    else if (c_sel == 2) C = g_gx2;
    else                 C = g_z;

    const int tid = threadIdx.x, lane = tid & 31, w = tid >> 5;
    const int wm = w >> 1, wn = w & 1;
    const int m0 = blockIdx.y * 128, n0 = blockIdx.x * 64;
    const int g = lane >> 2, c = lane & 3;

    float acc[2][4][4];
    #pragma unroll
    for (int mt = 0; mt < 2; mt++)
        #pragma unroll
        for (int nt = 0; nt < 4; nt++)
            #pragma unroll
            for (int e = 0; e < 4; e++) acc[mt][nt][e] = 0.f;

    const int ktiles = (K + 15) >> 4;

    if ((K & 3) == 0) {
        // ---- 3-stage cp.async pipeline ----
        const int arow = tid >> 1, akq = (tid & 1) * 8;       // A: 2 chunks/thread
        const int wrow = tid >> 2, wkq = (tid & 3) * 4;       // W: 1 chunk/thread

        auto issue_tile = [&](int kt) {
            const int kb = kt << 4;
            const int bf = kt % 3;
            const float* s0 = &A[(size_t)(m0 + arow) * K + kb + akq];
            const int r0 = clamp16((K - kb - akq) * 4);
            const int r1 = clamp16((K - kb - akq - 4) * 4);
            cpa16(&As[bf][arow][akq], r0 ? s0 : A, r0);
            cpa16(&As[bf][arow][akq + 4], r1 ? s0 + 4 : A, r1);
            const float* sw = &W[(size_t)(n0 + wrow) * K + kb + wkq];
            const int rw = clamp16((K - kb - wkq) * 4);
            cpa16(&Ws[bf][wrow][wkq], rw ? sw : W, rw);
            asm volatile("cp.async.commit_group;");
        };

        issue_tile(0);
        if (ktiles > 1) issue_tile(1);

        for (int kt = 0; kt < ktiles; kt++) {
            if (kt + 1 < ktiles) { asm volatile("cp.async.wait_group 1;"); }
            else                 { asm volatile("cp.async.wait_group 0;"); }
            __syncthreads();   // everyone's tile-kt copies visible; prior reads of
                               // buf (kt+2)%3 (= compute kt-1) are globally done
            gemm_compute(As[kt % 3], Ws[kt % 3], acc, wm, wn, g, c);
            if (kt + 2 < ktiles) issue_tile(kt + 2);
        }
    } else {
        // ---- generic path (small K: 74, 35) ----
        const int k = tid & 15, mi = tid >> 4;
        for (int kt = 0; kt < ktiles; kt++) {
            const int kb = kt << 4;
            #pragma unroll
            for (int p = 0; p < 8; p++) {
                const int m = mi + p * 16;
                As[0][m][k] = (kb + k < K) ? A[(size_t)(m0 + m) * K + kb + k] : 0.f;
            }
            #pragma unroll
            for (int p = 0; p < 4; p++) {
                const int n = mi + p * 16;
                Ws[0][n][k] = (kb + k < K) ? W[(size_t)(n0 + n) * K + kb + k] : 0.f;
            }
            __syncthreads();
            gemm_compute(As[0], Ws[0], acc, wm, wn, g, c);
            __syncthreads();
        }
    }

    #pragma unroll
    for (int mt = 0; mt < 2; mt++) {
        #pragma unroll
        for (int nt = 0; nt < 4; nt++) {
            const int nc = n0 + wn * 32 + nt * 8 + c * 2;
            float bb0 = b1[nc], bb1 = b1[nc + 1];
            if (b2) { bb0 += b2[nc]; bb1 += b2[nc + 1]; }
            #pragma unroll
            for (int hf = 0; hf < 2; hf++) {
                const int mr = m0 + wm * 32 + mt * 16 + g + hf * 8;
                float v0 = acc[mt][nt][hf * 2 + 0] + bb0;
                float v1 = acc[mt][nt][hf * 2 + 1] + bb1;
                if (relu) { v0 = fmaxf(v0, 0.f); v1 = fmaxf(v1, 0.f); }
                float2 st = make_float2(v0, v1);
                *(float2*)&C[(size_t)mr * N + nc] = st;
            }
        }
    }
}

// ------------------------------------------------------------------------------
// Recurrence bf16 mma inner loop; 4-deep register-ring prefetch (8 LDG.128).
// ------------------------------------------------------------------------------
template<int KG>
__device__ __forceinline__ void rec_mma(
    float (&acc)[2][2][4], const uint4* __restrict__ hbp,
    int tb0, int tb1, int lane,
    const uint* __restrict__ wsp, int wld, int g, int c)
{
    uint4 R0[4], R1[4];
    #pragma unroll
    for (int p = 0; p < 4; p++) {
        R0[p] = __ldcg(hbp + (tb0 + p) * 32 + lane);
        R1[p] = __ldcg(hbp + (tb1 + p) * 32 + lane);
    }
    #pragma unroll
    for (int kg = 0; kg < KG; kg++) {
        const int s = kg & 3;
        const uint4 a0 = R0[s], a1 = R1[s];
        if (kg + 4 < KG) {
            R0[s] = __ldcg(hbp + (tb0 + kg + 4) * 32 + lane);
            R1[s] = __ldcg(hbp + (tb1 + kg + 4) * 32 + lane);
        }
        #pragma unroll
        for (int nt = 0; nt < 2; nt++) {
            const uint b0 = wsp[(nt * 8 + g) * wld + kg * 8 + c];
            const uint b1 = wsp[(nt * 8 + g) * wld + kg * 8 + 4 + c];
            mma16(acc[0][nt], a0, b0, b1);
            mma16(acc[1][nt], a1, b0, b1);
        }
    }
}

// ------------------------------------------------------------------------------
// Persistent LSTM recurrence (bf16 tensor cores). 128 CTAs x 256 threads.
// CTA owns 4 cells of layer0 (unit A, warps 0-3) and 4 cells of layer1/2
// (unit B, warps 4-7). Cell state in registers; release/acquire grid barrier;
// paired bf16x2 h-stores; gx loads for t+1 hoisted over the barrier wait.
// ------------------------------------------------------------------------------
__global__ void __launch_bounds__(256, 1) lstm_rec(
    const float* __restrict__ Whh0,
    const float* __restrict__ Whh1,
    const float* __restrict__ Whh2)
{
    extern __shared__ uint smu[];
    uint*  wsA = smu;                        // [16][260]  bf16x2 B-fragment words
    uint*  wsB = wsA + 16 * 260;             // [16][132]
    float* gsA = (float*)(wsB + 16 * 132);   // [16][132] gate preacts fp32
    float* gsB = gsA + 16 * 132;             // [16][132]
    float* hstage = gsB + 16 * 132;          // [8][132]  h values for coalesced hcat write

    const int cta = blockIdx.x, tid = threadIdx.x;
    const int lane = tid & 31, w = tid >> 5;
    const int cbA = cta * 4;

    const float* WB; const float* gxB; int coloffB, cbB, lbB_elem, lbB_u4;
    if (cta < 64) { WB = Whh1; gxB = g_gx1; coloffB = 512; cbB = cta * 4;        lbB_elem = 65536; lbB_u4 = 8192; }
    else          { WB = Whh2; gxB = g_gx2; coloffB = 768; cbB = (cta - 64) * 4; lbB_elem = 98304; lbB_u4 = 12288; }

    // ---- one-time weight stage: pack bf16x2 B-fragment words ----
    for (int i = tid; i < 16 * 256; i += 256) {
        const int jj = i >> 8, ww = i & 255;
        const int kg = ww >> 3, sub = ww & 7;
        const int k = kg * 16 + (sub >> 2) * 8 + (sub & 3) * 2;
        const float* row = &Whh0[(size_t)((jj >> 2) * 512 + cbA + (jj & 3)) * 512];
        wsA[jj * 260 + ww] = pack_bf16x2(row[k], row[k + 1]);
    }
    for (int i = tid; i < 16 * 128; i += 256) {
        const int jj = i >> 7, ww = i & 127;
        const int kg = ww >> 3, sub = ww & 7;
        const int k = kg * 16 + (sub >> 2) * 8 + (sub & 3) * 2;
        const float* row = &WB[(size_t)((jj >> 2) * 256 + cbB + (jj & 3)) * 256];
        wsB[jj * 132 + ww] = pack_bf16x2(row[k], row[k + 1]);
    }
    __syncthreads();

    const bool isA = (w < 4);
    const int  wl  = isA ? w : w - 4;
    const uint* wsp = isA ? wsA : wsB;
    const int  wld = isA ? 260 : 132;
    float* gsp = isA ? gsA : gsB;
    const int  lw_u4 = isA ? 0 : lbB_u4;

    const int b_e = tid & 127, top = tid >> 7;
    const int g = lane >> 2, c = lane & 3;

    float creg[2][2] = {{0.f, 0.f}, {0.f, 0.f}};   // cell state in registers

    float4 gvA[2], gvB[2];
    auto load_gx = [&](int t) {
        const size_t rowA = ((size_t)(b_e * TSTEPS + t)) << 11;
        const size_t rowB = ((size_t)(b_e * TSTEPS + t)) << 10;
        #pragma unroll
        for (int cp = 0; cp < 2; cp++) {
            const int gg = top + cp * 2;
            gvA[cp] = *(const float4*)&g_gx0[rowA + gg * 512 + cbA];
            gvB[cp] = *(const float4*)&gxB [rowB + gg * 256 + cbB];
        }
    };
    load_gx(0);

    for (int t = 0; t < TSTEPS; t++) {
        float acc[2][2][4];
        if (t > 0) {
            #pragma unroll
            for (int m = 0; m < 2; m++)
                #pragma unroll
                for (int nt = 0; nt < 2; nt++)
                    #pragma unroll
                    for (int e = 0; e < 4; e++) acc[m][nt][e] = 0.f;

            const uint4* hbp = (const uint4*)(g_hb[(t - 1) & 1]) + lw_u4;
            if (isA) rec_mma<32>(acc, hbp, (wl * 2 + 0) * 32, (wl * 2 + 1) * 32, lane, wsp, wld, g, c);
            else     rec_mma<16>(acc, hbp, (wl * 2 + 0) * 16, (wl * 2 + 1) * 16, lane, wsp, wld, g, c);
        }

        // ---- stage gx into gate smem (disjoint ownership) ----
        #pragma unroll
        for (int cp = 0; cp < 2; cp++) {
            const int gg = top + cp * 2;
            gsA[(gg * 4 + 0) * 132 + b_e] = gvA[cp].x;
            gsA[(gg * 4 + 1) * 132 + b_e] = gvA[cp].y;
            gsA[(gg * 4 + 2) * 132 + b_e] = gvA[cp].z;
            gsA[(gg * 4 + 3) * 132 + b_e] = gvA[cp].w;
            gsB[(gg * 4 + 0) * 132 + b_e] = gvB[cp].x;
            gsB[(gg * 4 + 1) * 132 + b_e] = gvB[cp].y;
            gsB[(gg * 4 + 2) * 132 + b_e] = gvB[cp].z;
            gsB[(gg * 4 + 3) * 132 + b_e] = gvB[cp].w;
        }
        __syncthreads();

        // ---- accumulate mma into gate smem (disjoint per thread) ----
        if (t > 0) {
            #pragma unroll
            for (int m = 0; m < 2; m++) {
                const int r0 = wl * 32 + m * 16 + g;
                #pragma unroll
                for (int nt = 0; nt < 2; nt++) {
                    const int c0 = nt * 8 + c * 2;
                    gsp[ c0      * 132 + r0    ] += acc[m][nt][0];
                    gsp[(c0 + 1) * 132 + r0    ] += acc[m][nt][1];
                    gsp[ c0      * 132 + r0 + 8] += acc[m][nt][2];
                    gsp[(c0 + 1) * 132 + r0 + 8] += acc[m][nt][3];
                }
            }
        }
        __syncthreads();

        // ---- cell update + paired bf16x2 h stores (c in registers) ----
        uint* hbw32 = (uint*)(g_hb[t & 1]);
        #pragma unroll
        for (int u = 0; u < 2; u++) {
            float* gs = u ? gsB : gsA;
            const int cb  = u ? cbB : cbA;
            const int lbE = u ? lbB_elem : 0;
            const int KGu = u ? 16 : 32;
            float hn2[2];
            #pragma unroll
            for (int cp = 0; cp < 2; cp++) {
                const int cc = top * 2 + cp;
                const float gi = gs[( 0 + cc) * 132 + b_e];
                const float gf = gs[( 4 + cc) * 132 + b_e];
                const float gg = gs[( 8 + cc) * 132 + b_e];
                const float go = gs[(12 + cc) * 132 + b_e];
                const float cold = creg[u][cp];
                const float cn = sigf(gf) * cold + sigf(gi) * tanhfast(gg);
                const float hn = sigf(go) * tanhfast(cn);
                creg[u][cp] = cn;
                hn2[cp] = hn;
                hstage[(u * 4 + cc) * 132 + b_e] = hn;
            }
            // one 4B store per unit: cells (top*2, top*2+1) are adjacent bf16 in
            // the fragment word (same lane_w, same reg, pos = cp; base even)
            const int col = cb + top * 2;
            const int kg = col >> 4, c16 = col & 15;
            const int blk = b_e >> 4, rl = b_e & 15;
            const int lane_w = (rl & 7) * 4 + ((c16 & 7) >> 1);
            const int reg = (rl >> 3) + 2 * (c16 >> 3);
            const int off = lbE + (blk * KGu + kg) * 256 + lane_w * 8 + reg * 2;
            hbw32[off >> 1] = pack_bf16x2(hn2[0], hn2[1]);
        }
        __syncthreads();   // hstage ready; all g_hb stores issued

        // ---- release barrier signal early (orders g_hb stores, CG pattern) ----
        if (t < TSTEPS - 1 && tid == 0) {
            asm volatile("st.release.gpu.u32 [%0], %1;"
                         :: "l"(g_flags + cta), "r"((unsigned)(t + 1)) : "memory");
        }

        // ---- prefetch next step's gx (barrier-independent) ----
        if (t + 1 < TSTEPS) load_gx(t + 1);

        // ---- coalesced float4 g_hcat write (not ordered by barrier; FC1-only) ----
        {
            const int uu = top;
            const int cb  = uu ? cbB : cbA;
            const int col = uu ? coloffB : 0;
            float4 hv;
            hv.x = hstage[(uu * 4 + 0) * 132 + b_e];
            hv.y = hstage[(uu * 4 + 1) * 132 + b_e];
            hv.z = hstage[(uu * 4 + 2) * 132 + b_e];
            hv.w = hstage[(uu * 4 + 3) * 132 + b_e];
            *(float4*)&g_hcat[((size_t)(b_e * TSTEPS + t)) * 1024 + col + cb] = hv;
        }

        // ---- acquire-poll across the 128 resident CTAs ----
        if (t < TSTEPS - 1) {
            if (tid < 128) {
                unsigned v;
                while (true) {
                    asm volatile("ld.acquire.gpu.u32 %0, [%1];"
                                 : "=r"(v) : "l"(g_flags + tid) : "memory");
                    if (v >= (unsigned)(t + 1)) break;
                    __nanosleep(8);
                }
            }
            __syncthreads();
        }
    }
}

// ------------------------------------------------------------------------------
// FC2 (7x256) + log_softmax, one warp per (b,t) row.
// ------------------------------------------------------------------------------
__global__ __launch_bounds__(256) void fc2_softmax(
    const float* __restrict__ W2, const float* __restrict__ b2,
    float* __restrict__ out)
{
    const int warp = threadIdx.x >> 5, lane = threadIdx.x & 31;
    const int row = blockIdx.x * 8 + warp;
    const float4* z4 = (const float4*)&g_z[(size_t)row * 256];
    const float4 z0 = z4[lane];
    const float4 z1 = z4[32 + lane];

    float logit[7];
    #pragma unroll
    for (int o = 0; o < 7; o++) {
        const float4* w4 = (const float4*)&W2[o * 256];
        const float4 w0 = w4[lane], w1 = w4[32 + lane];
        float p = z0.x * w0.x + z0.y * w0.y + z0.z * w0.z + z0.w * w0.w
                + z1.x * w1.x + z1.y * w1.y + z1.z * w1.z + z1.w * w1.w;
        #pragma unroll
        for (int s = 16; s > 0; s >>= 1) p += __shfl_xor_sync(0xffffffffu, p, s);
        logit[o] = p + b2[o];
    }
    float m = logit[0];
    #pragma unroll
    for (int o = 1; o < 7; o++) m = fmaxf(m, logit[o]);
    float se = 0.f;
    #pragma unroll
    for (int o = 0; o < 7; o++) se += expf(logit[o] - m);
    const float lse = logf(se);
    if (lane < 7) out[(size_t)row * 7 + lane] = logit[lane] - m - lse;
}

// ------------------------------------------------------------------------------
extern "C" void kernel_launch(void* const* d_in, const int* in_sizes, int n_in,
                              void* d_out, int out_size)
{
    const float* x0    = (const float*)d_in[0];
    const float* x1    = (const float*)d_in[1];
    const float* x2    = (const float*)d_in[2];
    const float* Wih0  = (const float*)d_in[3];
    const float* Whh0  = (const float*)d_in[4];
    const float* bih0  = (const float*)d_in[5];
    const float* bhh0  = (const float*)d_in[6];
    const float* Wih1  = (const float*)d_in[7];
    const float* Whh1  = (const float*)d_in[8];
    const float* bih1  = (const float*)d_in[9];
    const float* bhh1  = (const float*)d_in[10];
    const float* Wih2  = (const float*)d_in[11];
    const float* Whh2  = (const float*)d_in[12];
    const float* bih2  = (const float*)d_in[13];
    const float* bhh2  = (const float*)d_in[14];
    const float* fcW1  = (const float*)d_in[15];
    const float* fcb1  = (const float*)d_in[16];
    const float* fcW2  = (const float*)d_in[17];
    const float* fcb2  = (const float*)d_in[18];
    float* out = (float*)d_out;

    const int rec_smem = (16 * 260 + 16 * 132 + 2 * 16 * 132 + 8 * 132) * 4;
    cudaFuncSetAttribute(lstm_rec, cudaFuncAttributeMaxDynamicSharedMemorySize, rec_smem);

    reset_kernel<<<1, 128>>>();

    // input projections: gx = x @ W_ih^T + b_ih + b_hh   (bf16 mma, cp.async pipe)
    { dim3 g(2048 / 64, BT / 128); gemm_bf16<<<g, 256>>>(x0, -1, Wih0, bih0, bhh0, 0, BT, 2048, 300, 0); }
    { dim3 g(1024 / 64, BT / 128); gemm_bf16<<<g, 256>>>(x1, -1, Wih1, bih1, bhh1, 1, BT, 1024,  74, 0); }
    { dim3 g(1024 / 64, BT / 128); gemm_bf16<<<g, 256>>>(x2, -1, Wih2, bih2, bhh2, 2, BT, 1024,  35, 0); }

    // persistent recurrence over T=256 (bf16 tensor cores, 128 CTAs)
    lstm_rec<<<128, 256, rec_smem>>>(Whh0, Whh1, Whh2);

    // FC1 + ReLU: z = relu(hcat @ fc_W1^T + fc_b1)
    { dim3 g(256 / 64, BT / 128); gemm_bf16<<<g, 256>>>(nullptr, 0, fcW1, fcb1, nullptr, 3, BT, 256, 1024, 1); }

    // FC2 + log_softmax
    fc2_softmax<<<BT / 8, 256>>>(fcW2, fcb2, out);
}